// round 10
// baseline (speedup 1.0000x reference)
#include <cuda_runtime.h>
#include <cuda_bf16.h>
#include <cstdint>

// ---------------- problem constants ----------------
#define DB 2
#define DS 2048
#define DD 512
#define DM 64
#define DT 2112              // DM + DS
#define DN 4224              // DB * DT
#define DH 8
#define DHD 64
#define DWIN 512
#define NSPLIT 11
#define SPLITROWS 384        // DN / NSPLIT = 384 (6 chunks of 64)
#define NLAY 2
#define LRC 1e-3f
#define WDC 1e-2f
#define EPSC 1e-8f
#define MAXALR 0.01f

// warp-mma tile constants
#define ROWB 144             // bytes per smem tile row (64 bf16 = 128B + 16B pad)
#define TILEB (128 * ROWB)   // 18432 B per tile
#define WM_SMEM (4 * TILEB)  // Ah, Al, Bh, Bl = 73728 B
#define ATILEB (64 * ROWB)   // 9216 B attention tile

// ---------------- scratch (device globals; no allocs allowed) ----------------
static __device__ float g_XM[DN * DD];
static __device__ float g_K[DN * DD];
static __device__ float g_V[DN * DD];
static __device__ float g_Q[DN * DD];
static __device__ float g_LR[DN];
static __device__ float g_Z0[DN * DD];
static __device__ float g_X1[DN * DD];
static __device__ float g_Z1[DN * DD];
static __device__ float g_X2[DN * DD];
static __device__ float g_DY2[DN * DD];
static __device__ float g_DZ1[DN * DD];
static __device__ float g_DX1[DN * DD];
static __device__ float g_DZ0[DN * DD];
static __device__ float g_Wn[NLAY * DD * DD];
static __device__ float g_W1t[DD * DD];
static __device__ float g_Y1[DN * DD];
static __device__ float g_Y2[DN * DD];
static __device__ float g_AQ[DN * DD];
static __device__ float g_AK[DN * DD];
static __device__ float g_AV[DN * DD];
static __device__ float g_AO[DN * DD];
static __device__ float g_S[DB * DH * DT * DWIN];               // banded scores/probs
static __device__ float g_GP[NLAY * NSPLIT * DD * DD];          // split-K grad partials

__device__ __forceinline__ float sigf(float z) { return 1.0f / (1.0f + __expf(-z)); }
__device__ __forceinline__ float silup(float z) {
    float s = sigf(z);
    return s * (1.0f + z * (1.0f - s));
}

// ================= warp-mma helpers (sm_80+ baseline PTX, no 'a' features) ======
__device__ __forceinline__ uint32_t smem_u32(const void* p) {
    uint32_t a;
    asm("{ .reg .u64 t; cvta.to.shared.u64 t, %1; cvt.u32.u64 %0, t; }" : "=r"(a) : "l"(p));
    return a;
}
__device__ __forceinline__ void mma16816(float* c, const uint32_t* a, const uint32_t* b) {
    asm volatile(
        "mma.sync.aligned.m16n8k16.row.col.f32.bf16.bf16.f32 "
        "{%0,%1,%2,%3}, {%4,%5,%6,%7}, {%8,%9}, {%0,%1,%2,%3};"
        : "+f"(c[0]), "+f"(c[1]), "+f"(c[2]), "+f"(c[3])
        : "r"(a[0]), "r"(a[1]), "r"(a[2]), "r"(a[3]), "r"(b[0]), "r"(b[1]));
}
__device__ __forceinline__ void ldsm4(uint32_t* r, uint32_t addr) {
    asm volatile("ldmatrix.sync.aligned.m8n8.x4.shared.b16 {%0,%1,%2,%3}, [%4];"
                 : "=r"(r[0]), "=r"(r[1]), "=r"(r[2]), "=r"(r[3]) : "r"(addr));
}
__device__ __forceinline__ void ldsm2(uint32_t* r, uint32_t addr) {
    asm volatile("ldmatrix.sync.aligned.m8n8.x2.shared.b16 {%0,%1}, [%2];"
                 : "=r"(r[0]), "=r"(r[1]) : "r"(addr));
}
// fp32 pair -> bf16x2 hi + bf16x2 lo (split-bf16)
__device__ __forceinline__ void cvt_hl(float a, float b, uint32_t& h, uint32_t& l) {
    __nv_bfloat162 th, tl;
    th.x = __float2bfloat16(a);
    th.y = __float2bfloat16(b);
    tl.x = __float2bfloat16(a - __bfloat162float(th.x));
    tl.y = __float2bfloat16(b - __bfloat162float(th.y));
    h = *reinterpret_cast<uint32_t*>(&th);
    l = *reinterpret_cast<uint32_t*>(&tl);
}

// ---- staging: fp32 K-contig [row][k] source -> bf16 hi/lo tiles (128 rows x 64k)
__device__ __forceinline__ void stage_nt(const float* __restrict__ src, int row0, int k0,
                                         char* th, char* tl, int tid) {
#pragma unroll
    for (int it = 0; it < 8; it++) {
        int idx = tid + (it << 8);            // 0..2047 float4s
        int m = idx >> 4;                     // 16 float4 per row
        int kq = (idx & 15) << 2;             // 0..60
        float4 v = *(const float4*)&src[(row0 + m) * DD + k0 + kq];
        uint32_t h0, l0, h1, l1;
        cvt_hl(v.x, v.y, h0, l0);
        cvt_hl(v.z, v.w, h1, l1);
        uint32_t off = m * ROWB + (kq << 1);  // 8B aligned
        *(uint2*)(th + off) = make_uint2(h0, h1);
        *(uint2*)(tl + off) = make_uint2(l0, l1);
    }
}
// ---- staging transposed: tile(row=i, k) = src[(kb+k)*DD + col0 + i]
__device__ __forceinline__ void stage_tn(const float* __restrict__ src, int col0, int kb,
                                         char* th, char* tl, int tid) {
    const int i = tid & 127;
    const int half = tid >> 7;                // 0,1
#pragma unroll
    for (int it = 0; it < 16; it++) {
        int k = (it << 2) + (half << 1);      // even 0..62
        float v0 = src[(kb + k) * DD + col0 + i];
        float v1 = src[(kb + k + 1) * DD + col0 + i];
        uint32_t h, l;
        cvt_hl(v0, v1, h, l);
        uint32_t off = i * ROWB + (k << 1);
        *(uint32_t*)(th + off) = h;
        *(uint32_t*)(tl + off) = l;
    }
}

// ================= 128x128 warp-mma GEMM body =================
// MODE 0 = NT: C[M,N] = A[M,512] @ W[N,512]^T   (8 chunks of 64)
// MODE 1 = TN: C[i,j] = sum_n A[n,i] W[n,j] over split z (6 chunks of 64)
// EPI 0: Cz = z ; 1: Cz = z, Cx = A + silu(z) ; 2: d_out drop-meta ; 3: Cz = z + R
template <int MODE, int EPI>
__device__ void wm_body(const float* __restrict__ A, const float* __restrict__ W,
                        const float* __restrict__ R, float* __restrict__ Cz,
                        float* __restrict__ Cx) {
    extern __shared__ char sm[];
    char* tAh = sm;
    char* tAl = sm + TILEB;
    char* tBh = sm + 2 * TILEB;
    char* tBl = sm + 3 * TILEB;
    const uint32_t sb = smem_u32(sm);

    const int tid = threadIdx.x;
    const int warp = tid >> 5, lane = tid & 31;
    const int wm = warp >> 2, wn = warp & 3;       // 2 x 4 warp grid
    const int m0 = blockIdx.x << 7;
    const int n0 = blockIdx.y << 7;
    const int kb0 = (MODE == 1) ? blockIdx.z * SPLITROWS : 0;
    const int NCH = (MODE == 1) ? (SPLITROWS / 64) : (DD / 64);
    float* Czp = (MODE == 1) ? (Cz + blockIdx.z * DD * DD) : Cz;

    float acc[4][4][4];
#pragma unroll
    for (int mf = 0; mf < 4; mf++)
#pragma unroll
        for (int nf = 0; nf < 4; nf++)
#pragma unroll
            for (int e = 0; e < 4; e++) acc[mf][nf][e] = 0.0f;

    // ldmatrix lane addressing
    const int ar = (lane & 7) + ((lane >> 3) & 1) * 8;
    const int acol = (lane >> 4) << 3;
    const int br = lane & 7;
    const int bcol = ((lane >> 3) & 1) << 3;
    const uint32_t aBase = sb + (wm * 64 + ar) * ROWB + acol * 2;
    const uint32_t bBase = sb + 2 * TILEB + (wn * 32 + br) * ROWB + bcol * 2;

    for (int c = 0; c < NCH; c++) {
        const int k0 = kb0 + (c << 6);
        if (MODE == 0) {
            stage_nt(A, m0, k0, tAh, tAl, tid);
            stage_nt(W, n0, k0, tBh, tBl, tid);
        } else {
            stage_tn(A, m0, k0, tAh, tAl, tid);
            stage_tn(W, n0, k0, tBh, tBl, tid);
        }
        __syncthreads();
#pragma unroll
        for (int ks = 0; ks < 4; ks++) {
            const uint32_t kOff = (uint32_t)(ks << 5);
            uint32_t ah[4][4], al[4][4], bh[4][2], bl[4][2];
#pragma unroll
            for (int mf = 0; mf < 4; mf++) {
                ldsm4(ah[mf], aBase + mf * (16 * ROWB) + kOff);
                ldsm4(al[mf], aBase + TILEB + mf * (16 * ROWB) + kOff);
            }
#pragma unroll
            for (int nf = 0; nf < 4; nf++) {
                ldsm2(bh[nf], bBase + nf * (8 * ROWB) + kOff);
                ldsm2(bl[nf], bBase + TILEB + nf * (8 * ROWB) + kOff);
            }
#pragma unroll
            for (int mf = 0; mf < 4; mf++)
#pragma unroll
                for (int nf = 0; nf < 4; nf++) {
                    mma16816(acc[mf][nf], ah[mf], bh[nf]);
                    mma16816(acc[mf][nf], ah[mf], bl[nf]);
                    mma16816(acc[mf][nf], al[mf], bh[nf]);
                }
        }
        __syncthreads();
    }

    const int erow = (lane >> 2);
    const int ecol = (lane & 3) << 1;
#pragma unroll
    for (int mf = 0; mf < 4; mf++)
#pragma unroll
        for (int nf = 0; nf < 4; nf++) {
            const int colg = n0 + wn * 32 + nf * 8 + ecol;
#pragma unroll
            for (int h = 0; h < 2; h++) {
                const int rowg = m0 + wm * 64 + mf * 16 + erow + h * 8;
                float zx = acc[mf][nf][2 * h];
                float zy = acc[mf][nf][2 * h + 1];
                if (EPI == 0) {
                    *(float2*)&Czp[rowg * DD + colg] = make_float2(zx, zy);
                } else if (EPI == 1) {
                    *(float2*)&Czp[rowg * DD + colg] = make_float2(zx, zy);
                    float2 a = *(const float2*)&A[rowg * DD + colg];
                    *(float2*)&Cx[rowg * DD + colg] =
                        make_float2(a.x + zx * sigf(zx), a.y + zy * sigf(zy));
                } else if (EPI == 3) {
                    float2 r = *(const float2*)&R[rowg * DD + colg];
                    *(float2*)&Czp[rowg * DD + colg] = make_float2(zx + r.x, zy + r.y);
                } else {
                    const int bb = rowg / DT, t = rowg - bb * DT;
                    if (t >= DM)
                        *(float2*)&Cx[(bb * DS + (t - DM)) * DD + colg] = make_float2(zx, zy);
                }
            }
        }
}

template <int MODE, int EPI>
__global__ void __launch_bounds__(256, 1) wm_gemm_k(
    const float* __restrict__ A, const float* __restrict__ W,
    const float* __restrict__ R, float* __restrict__ Cz, float* __restrict__ Cx) {
    wm_body<MODE, EPI>(A, W, R, Cz, Cx);
}

__global__ void __launch_bounds__(256, 1) wm_nt3_k(
    const float* __restrict__ A,
    const float* __restrict__ W0, const float* __restrict__ W1, const float* __restrict__ W2,
    float* __restrict__ C0, float* __restrict__ C1, float* __restrict__ C2) {
    const float* W = (blockIdx.z == 0) ? W0 : (blockIdx.z == 1 ? W1 : W2);
    float* C = (blockIdx.z == 0) ? C0 : (blockIdx.z == 1 ? C1 : C2);
    wm_body<0, 0>(A, W, nullptr, C, nullptr);
}

// ---------------- 512x512 transpose (for NN -> NT) ----------------
__global__ void transpose_k(const float* __restrict__ in, float* __restrict__ outp) {
    __shared__ float t[32][33];
    int x = blockIdx.x * 32 + threadIdx.x;
    int y = blockIdx.y * 32 + threadIdx.y;
#pragma unroll
    for (int j = 0; j < 32; j += 8) t[threadIdx.y + j][threadIdx.x] = in[(y + j) * DD + x];
    __syncthreads();
    x = blockIdx.y * 32 + threadIdx.x;
    y = blockIdx.x * 32 + threadIdx.y;
#pragma unroll
    for (int j = 0; j < 32; j += 8) outp[(y + j) * DD + x] = t[threadIdx.x][threadIdx.y + j];
}

// ---------------- build xm = concat(meta, x) ----------------
__global__ void build_xm_k(const float* __restrict__ x, const float* __restrict__ meta,
                           float* __restrict__ XM) {
    int idx = blockIdx.x * blockDim.x + threadIdx.x;
    if (idx >= DN * DD / 4) return;
    int e = idx << 2;
    int n = e / DD, d = e - n * DD;
    int b = n / DT, t = n - b * DT;
    float4 v;
    if (t < DM) v = *(const float4*)&meta[t * DD + d];
    else        v = *(const float4*)&x[(b * DS + (t - DM)) * DD + d];
    *(float4*)&XM[e] = v;
}

// ---------------- adaptive lr ----------------
__global__ void lr_proj_k(const float* __restrict__ XM, const float* __restrict__ wlr,
                          float* __restrict__ out) {
    int warp = (blockIdx.x * blockDim.x + threadIdx.x) >> 5;
    int lane = threadIdx.x & 31;
    if (warp >= DN) return;
    const float* xr = XM + warp * DD;
    float s = 0.0f;
#pragma unroll
    for (int i = 0; i < DD / 32; i++) s = fmaf(xr[lane + i * 32], wlr[lane + i * 32], s);
#pragma unroll
    for (int o = 16; o > 0; o >>= 1) s += __shfl_xor_sync(0xffffffffu, s, o);
    if (lane == 0) out[warp] = MAXALR * sigf(s);
}

// ---------------- head gradient + layer1 act backward ----------------
__global__ void grad_head_k(const float* __restrict__ X2, const float* __restrict__ Vv,
                            const float* __restrict__ Z1, const float* __restrict__ LRv,
                            float* __restrict__ DY2, float* __restrict__ DZ1) {
    int i = blockIdx.x * blockDim.x + threadIdx.x;
    if (i >= DN * DD) return;
    int n = i >> 9;
    float c = (2.0f / (float)DD) * LRv[n];
    float d2 = c * (X2[i] - Vv[i]);
    DY2[i] = d2;
    DZ1[i] = d2 * silup(Z1[i]);
}

__global__ void bwd_act0_k(const float* __restrict__ DX1, const float* __restrict__ Z0,
                           float* __restrict__ DZ0) {
    int i = blockIdx.x * blockDim.x + threadIdx.x;
    if (i >= DN * DD) return;
    DZ0[i] = DX1[i] * silup(Z0[i]);
}

// ---------------- reduce split-K partials + AdamW ----------------
__global__ void adamw_k(const float* __restrict__ W, float* __restrict__ Wn) {
    int idx = blockIdx.x * blockDim.x + threadIdx.x;
    if (idx >= NLAY * DD * DD) return;
    int l = idx / (DD * DD);
    int e = idx - l * (DD * DD);
    const float* gp = g_GP + l * NSPLIT * DD * DD;
    float g = 0.0f;
#pragma unroll
    for (int s = 0; s < NSPLIT; s++) g += gp[s * DD * DD + e];
    g *= (1.0f / 16.0f);
    float w = W[idx];
    Wn[idx] = w * (1.0f - LRC * WDC) - LRC * g / (fabsf(g) + EPSC);
}

// ================= attention on tensor cores (split-bf16 3-term) =================
// stage a 64x64 fp32 block (row-contiguous source) into bf16 hi/lo tiles
__device__ __forceinline__ void stage_att(const float* __restrict__ src,
                                          char* th, char* tl, int tid) {
#pragma unroll
    for (int it = 0; it < 4; it++) {
        int idx = tid + (it << 8);            // 0..1023 float4s
        int r = idx >> 4;
        int c4 = (idx & 15) << 2;
        float4 v = *(const float4*)&src[r * DD + c4];
        uint32_t h0, l0, h1, l1;
        cvt_hl(v.x, v.y, h0, l0);
        cvt_hl(v.z, v.w, h1, l1);
        uint32_t off = r * ROWB + (c4 << 1);
        *(uint2*)(th + off) = make_uint2(h0, h1);
        *(uint2*)(tl + off) = make_uint2(l0, l1);
    }
}

// ---------------- attention scores: S = Q @ K^T * 0.125, banded ----------------
__global__ void __launch_bounds__(256, 1) attn_scores_mma_k(
    const float* __restrict__ AQ, const float* __restrict__ AK, float* __restrict__ Sb) {
    __shared__ __align__(16) char sQh[ATILEB];
    __shared__ __align__(16) char sQl[ATILEB];
    __shared__ __align__(16) char sKh[ATILEB];
    __shared__ __align__(16) char sKl[ATILEB];
    const int q0 = blockIdx.x << 6;
    const int h = blockIdx.y, b = blockIdx.z;
    const int tid = threadIdx.x;
    const int warp = tid >> 5, lane = tid & 31;
    const int wm = warp >> 1, wn = warp & 1;       // 4 x 2 warps; tile 16m x 32n

    stage_att(&AQ[(b * DT + q0) * DD + h * DHD], sQh, sQl, tid);
    __syncthreads();

    const int ar = (lane & 7) + ((lane >> 3) & 1) * 8;
    const int acol = (lane >> 4) << 3;
    const int br = lane & 7;
    const int bcol = ((lane >> 3) & 1) << 3;
    const uint32_t aBaseH = smem_u32(sQh) + (wm * 16 + ar) * ROWB + acol * 2;
    const uint32_t aBaseL = smem_u32(sQl) + (wm * 16 + ar) * ROWB + acol * 2;
    const uint32_t bBaseH = smem_u32(sKh) + (wn * 32 + br) * ROWB + bcol * 2;
    const uint32_t bBaseL = smem_u32(sKl) + (wn * 32 + br) * ROWB + bcol * 2;

    const int erow = (lane >> 2);
    const int ecol = (lane & 3) << 1;
    float* Srow = Sb + ((size_t)(b * DH + h) * DT) * DWIN;

    int kLo = q0 - (DWIN - 1);
    if (kLo < 0) kLo = 0;
    kLo &= ~63;
    for (int k0 = kLo; k0 <= q0; k0 += 64) {
        stage_att(&AK[(b * DT + k0) * DD + h * DHD], sKh, sKl, tid);
        __syncthreads();

        float acc[4][4];
#pragma unroll
        for (int nf = 0; nf < 4; nf++)
#pragma unroll
            for (int e = 0; e < 4; e++) acc[nf][e] = 0.0f;
#pragma unroll
        for (int ks = 0; ks < 4; ks++) {
            const uint32_t kOff = (uint32_t)(ks << 5);
            uint32_t ah[4], al[4], bh[4][2], bl[4][2];
            ldsm4(ah, aBaseH + kOff);
            ldsm4(al, aBaseL + kOff);
#pragma unroll
            for (int nf = 0; nf < 4; nf++) {
                ldsm2(bh[nf], bBaseH + nf * (8 * ROWB) + kOff);
                ldsm2(bl[nf], bBaseL + nf * (8 * ROWB) + kOff);
            }
#pragma unroll
            for (int nf = 0; nf < 4; nf++) {
                mma16816(acc[nf], ah, bh[nf]);
                mma16816(acc[nf], ah, bl[nf]);
                mma16816(acc[nf], al, bh[nf]);
            }
        }
        // masked banded store, scaled by 1/8
#pragma unroll
        for (int nf = 0; nf < 4; nf++) {
#pragma unroll
            for (int hh = 0; hh < 2; hh++) {
                const int q = q0 + wm * 16 + erow + hh * 8;
                const int k = k0 + wn * 32 + nf * 8 + ecol;
                const int w0 = k - q + (DWIN - 1);
#pragma unroll
                for (int e = 0; e < 2; e++) {
                    const int kk = k + e;
                    if (kk <= q && q - kk < DWIN)
                        Srow[(size_t)q * DWIN + w0 + e] = acc[nf][2 * hh + e] * 0.125f;
                }
            }
        }
        __syncthreads();
    }
}

// ---------------- attention softmax over band (unchanged) ----------------
__global__ void attn_softmax_k(float* __restrict__ Sb) {
    int gw = (blockIdx.x * blockDim.x + threadIdx.x) >> 5;
    int lane = threadIdx.x & 31;
    if (gw >= DB * DH * DT) return;
    int q = gw % DT;
    int wlo = DWIN - 1 - q;
    if (wlo < 0) wlo = 0;
    float* row = Sb + (size_t)gw * DWIN;
    float v[16];
    float m = -1e30f;
#pragma unroll
    for (int i = 0; i < 16; i++) {
        int w = lane + i * 32;
        v[i] = (w >= wlo) ? row[w] : -1e30f;
        m = fmaxf(m, v[i]);
    }
#pragma unroll
    for (int o = 16; o > 0; o >>= 1) m = fmaxf(m, __shfl_xor_sync(0xffffffffu, m, o));
    float sum = 0.0f;
#pragma unroll
    for (int i = 0; i < 16; i++) {
        int w = lane + i * 32;
        v[i] = (w >= wlo) ? __expf(v[i] - m) : 0.0f;
        sum += v[i];
    }
#pragma unroll
    for (int o = 16; o > 0; o >>= 1) sum += __shfl_xor_sync(0xffffffffu, sum, o);
    float inv = 1.0f / sum;
#pragma unroll
    for (int i = 0; i < 16; i++) {
        int w = lane + i * 32;
        if (w >= wlo) row[w] = v[i] * inv;
    }
}

// ---------------- attention P @ V on tensor cores ----------------
__global__ void __launch_bounds__(256, 1) attn_pv_mma_k(
    const float* __restrict__ Sb, const float* __restrict__ AV, float* __restrict__ AO) {
    __shared__ __align__(16) char sPh[ATILEB];
    __shared__ __align__(16) char sPl[ATILEB];
    __shared__ __align__(16) char sVh[ATILEB];   // transposed: [d][k]
    __shared__ __align__(16) char sVl[ATILEB];
    const int q0 = blockIdx.x << 6;
    const int h = blockIdx.y, b = blockIdx.z;
    const int tid = threadIdx.x;
    const int warp = tid >> 5, lane = tid & 31;
    const int wm = warp >> 1, wn = warp & 1;       // 4 x 2 warps; tile 16q x 32d

    const int ar = (lane & 7) + ((lane >> 3) & 1) * 8;
    const int acol = (lane >> 4) << 3;
    const int br = lane & 7;
    const int bcol = ((lane >> 3) & 1) << 3;
    const uint32_t aBaseH = smem_u32(sPh) + (wm * 16 + ar) * ROWB + acol * 2;
    const uint32_t aBaseL = smem_u32(sPl) + (wm * 16 + ar) * ROWB + acol * 2;
    const uint32_t bBaseH = smem_u32(sVh) + (wn * 32 + br) * ROWB + bcol * 2;
    const uint32_t bBaseL = smem_u32(sVl) + (wn * 32 + br) * ROWB + bcol * 2;

    const float* Srow = Sb + ((size_t)(b * DH + h) * DT) * DWIN;

    float acc[4][4];
#pragma unroll
    for (int nf = 0; nf < 4; nf++)
#pragma unroll
        for (int e = 0; e < 4; e++) acc[nf][e] = 0.0f;

    int kLo = q0 - (DWIN - 1);
    if (kLo < 0) kLo = 0;
    kLo &= ~63;
    for (int k0 = kLo; k0 <= q0; k0 += 64) {
        // stage P[q][k] 64x64 with band mask
#pragma unroll
        for (int it = 0; it < 8; it++) {
            int idx = tid + (it << 8);            // 0..2047 (64 rows x 32 pairs)
            int qi = idx >> 5;
            int pk = (idx & 31) << 1;
            int q = q0 + qi, k = k0 + pk;
            int w0 = k - q + (DWIN - 1);
            float p0 = (k <= q && q - k < DWIN) ? Srow[(size_t)q * DWIN + w0] : 0.0f;
            float p1 = (k + 1 <= q && q - (k + 1) < DWIN) ? Srow[(size_t)q * DWIN + w0 + 1] : 0.0f;
            uint32_t hh, ll;
            cvt_hl(p0, p1, hh, ll);
            uint32_t off = qi * ROWB + (pk << 1);
            *(uint32_t*)(sPh + off) = hh;
            *(uint32_t*)(sPl + off) = ll;
        }
        // stage V transposed: sV[d][k] = AV[(b*DT + k0+k)*DD + h*DHD + d]
        {
            const int d = tid & 63;
            const int grp = tid >> 6;             // 0..3, each 16 ks
            const float* vb = &AV[(size_t)(b * DT + k0) * DD + h * DHD + d];
#pragma unroll
            for (int it = 0; it < 8; it++) {
                int k = (grp << 4) + (it << 1);
                float v0 = vb[(size_t)k * DD];
                float v1 = vb[(size_t)(k + 1) * DD];
                uint32_t hh, ll;
                cvt_hl(v0, v1, hh, ll);
                uint32_t off = d * ROWB + (k << 1);
                *(uint32_t*)(sVh + off) = hh;
                *(uint32_t*)(sVl + off) = ll;
            }
        }
        __syncthreads();
#pragma unroll
        for (int ks = 0; ks < 4; ks++) {
            const uint32_t kOff = (uint32_t)(ks << 5);
            uint32_t ah[4], al[4], bh[4][2], bl[4][2];
            ldsm4(ah, aBaseH + kOff);
            ldsm4(al, aBaseL + kOff);
#pragma unroll
            for (int nf = 0; nf < 4; nf++) {
                ldsm2(bh[nf], bBaseH + nf * (8 * ROWB) + kOff);
                ldsm2(bl[nf], bBaseL + nf * (8 * ROWB) + kOff);
            }
#pragma unroll
            for (int nf = 0; nf < 4; nf++) {
                mma16816(acc[nf], ah, bh[nf]);
                mma16816(acc[nf], ah, bl[nf]);
                mma16816(acc[nf], al, bh[nf]);
            }
        }
        __syncthreads();
    }

    const int erow = (lane >> 2);
    const int ecol = (lane & 3) << 1;
#pragma unroll
    for (int nf = 0; nf < 4; nf++) {
        const int d = wn * 32 + nf * 8 + ecol;
#pragma unroll
        for (int hh = 0; hh < 2; hh++) {
            const int q = q0 + wm * 16 + erow + hh * 8;
            *(float2*)&AO[(size_t)(b * DT + q) * DD + h * DHD + d] =
                make_float2(acc[nf][2 * hh], acc[nf][2 * hh + 1]);
        }
    }
}

// ---------------- host ----------------
extern "C" void kernel_launch(void* const* d_in, const int* in_sizes, int n_in,
                              void* d_out, int out_size) {
    const float* x      = (const float*)d_in[0];
    const float* meta   = (const float*)d_in[1];
    const float* lmm_w  = (const float*)d_in[2];
    const float* w_q    = (const float*)d_in[3];
    const float* w_k    = (const float*)d_in[4];
    const float* w_v    = (const float*)d_in[5];
    const float* w_lr   = (const float*)d_in[6];
    const float* swa_wq = (const float*)d_in[7];
    const float* swa_wk = (const float*)d_in[8];
    const float* swa_wv = (const float*)d_in[9];
    const float* swa_wo = (const float*)d_in[10];
    float* out = (float*)d_out;

    float *XM, *K, *V, *Q, *LR, *Z0, *X1, *Z1, *X2, *DY2, *DZ1, *DX1, *DZ0;
    float *Wn, *W1t, *Y1, *Y2, *AQ, *AK, *AV, *AO, *Sb, *GP;
    cudaGetSymbolAddress((void**)&XM, g_XM);
    cudaGetSymbolAddress((void**)&K, g_K);
    cudaGetSymbolAddress((void**)&V, g_V);
    cudaGetSymbolAddress((void**)&Q, g_Q);
    cudaGetSymbolAddress((void**)&LR, g_LR);
    cudaGetSymbolAddress((void**)&Z0, g_Z0);
    cudaGetSymbolAddress((void**)&X1, g_X1);
    cudaGetSymbolAddress((void**)&Z1, g_Z1);
    cudaGetSymbolAddress((void**)&X2, g_X2);
    cudaGetSymbolAddress((void**)&DY2, g_DY2);
    cudaGetSymbolAddress((void**)&DZ1, g_DZ1);
    cudaGetSymbolAddress((void**)&DX1, g_DX1);
    cudaGetSymbolAddress((void**)&DZ0, g_DZ0);
    cudaGetSymbolAddress((void**)&Wn, g_Wn);
    cudaGetSymbolAddress((void**)&W1t, g_W1t);
    cudaGetSymbolAddress((void**)&Y1, g_Y1);
    cudaGetSymbolAddress((void**)&Y2, g_Y2);
    cudaGetSymbolAddress((void**)&AQ, g_AQ);
    cudaGetSymbolAddress((void**)&AK, g_AK);
    cudaGetSymbolAddress((void**)&AV, g_AV);
    cudaGetSymbolAddress((void**)&AO, g_AO);
    cudaGetSymbolAddress((void**)&Sb, g_S);
    cudaGetSymbolAddress((void**)&GP, g_GP);

    cudaFuncSetAttribute(wm_nt3_k, cudaFuncAttributeMaxDynamicSharedMemorySize, WM_SMEM);
    cudaFuncSetAttribute(wm_gemm_k<0, 1>, cudaFuncAttributeMaxDynamicSharedMemorySize, WM_SMEM);
    cudaFuncSetAttribute(wm_gemm_k<0, 2>, cudaFuncAttributeMaxDynamicSharedMemorySize, WM_SMEM);
    cudaFuncSetAttribute(wm_gemm_k<0, 3>, cudaFuncAttributeMaxDynamicSharedMemorySize, WM_SMEM);
    cudaFuncSetAttribute(wm_gemm_k<1, 0>, cudaFuncAttributeMaxDynamicSharedMemorySize, WM_SMEM);

    const dim3 gG(DN / 128, DD / 128);          // 33 x 4
    const dim3 gG3(DN / 128, DD / 128, 3);      // batched projections
    const dim3 gTN(DD / 128, DD / 128, NSPLIT); // 4 x 4 x 11
    const dim3 gAT(DT / 64, DH, DB);            // 33 x 8 x 2
    const int EW = (DN * DD + 255) / 256;

    // 1. concat meta + x ; transpose W1 for the NN gemm
    build_xm_k<<<(DN * DD / 4 + 255) / 256, 256>>>(x, meta, XM);
    transpose_k<<<dim3(16, 16), dim3(32, 8)>>>(lmm_w + DD * DD, W1t);
    // 2. projections (K, V, Q batched)
    wm_nt3_k<<<gG3, 256, WM_SMEM>>>(XM, w_k, w_v, w_q, K, V, Q);
    lr_proj_k<<<(DN * 32 + 255) / 256, 256>>>(XM, w_lr, LR);
    // 3. LMM forward on keys
    wm_gemm_k<0, 1><<<gG, 256, WM_SMEM>>>(K, lmm_w, nullptr, Z0, X1);
    wm_gemm_k<0, 1><<<gG, 256, WM_SMEM>>>(X1, lmm_w + DD * DD, nullptr, Z1, X2);
    // 4. backward
    grad_head_k<<<EW, 256>>>(X2, V, Z1, LR, DY2, DZ1);
    wm_gemm_k<1, 0><<<gTN, 256, WM_SMEM>>>(DZ1, X1, nullptr, GP + NSPLIT * DD * DD, nullptr); // dW1
    wm_gemm_k<0, 3><<<gG, 256, WM_SMEM>>>(DZ1, W1t, DY2, DX1, nullptr);                       // dx1
    bwd_act0_k<<<EW, 256>>>(DX1, Z0, DZ0);
    wm_gemm_k<1, 0><<<gTN, 256, WM_SMEM>>>(DZ0, K, nullptr, GP, nullptr);                     // dW0
    // 5. AdamW first step
    adamw_k<<<(NLAY * DD * DD + 255) / 256, 256>>>(lmm_w, Wn);
    // 6. retrieval with updated weights
    wm_gemm_k<0, 1><<<gG, 256, WM_SMEM>>>(Q, Wn, nullptr, Z0, Y1);
    wm_gemm_k<0, 1><<<gG, 256, WM_SMEM>>>(Y1, Wn + DD * DD, nullptr, Z1, Y2);
    // 7. sliding-window attention (tensor-core scores + PV)
    wm_nt3_k<<<gG3, 256, WM_SMEM>>>(Y2, swa_wq, swa_wk, swa_wv, AQ, AK, AV);
    attn_scores_mma_k<<<gAT, 256>>>(AQ, AK, Sb);
    attn_softmax_k<<<(DB * DH * DT * 32 + 255) / 256, 256>>>(Sb);
    attn_pv_mma_k<<<gAT, 256>>>(Sb, AV, AO);
    // 8. output projection, dropping meta rows
    wm_gemm_k<0, 2><<<gG, 256, WM_SMEM>>>(AO, swa_wo, nullptr, nullptr, out);
}

// round 11
// speedup vs baseline: 1.2598x; 1.2598x over previous
#include <cuda_runtime.h>
#include <cuda_bf16.h>
#include <cstdint>

// ---------------- problem constants ----------------
#define DB 2
#define DS 2048
#define DD 512
#define DM 64
#define DT 2112              // DM + DS
#define DN 4224              // DB * DT
#define DH 8
#define DHD 64
#define DWIN 512
#define NSPLIT 11
#define SPLITROWS 384        // DN / NSPLIT = 384 (6 chunks of 64)
#define NLAY 2
#define LRC 1e-3f
#define WDC 1e-2f
#define EPSC 1e-8f
#define MAXALR 0.01f

// warp-mma tile constants
#define ROWB 144             // bytes per smem tile row (64 bf16 = 128B + 16B pad)
#define TILEB (128 * ROWB)   // 18432 B per tile
#define BUFB (4 * TILEB)     // Ah, Al, Bh, Bl = 73728 B per buffer
#define WM_SMEM (2 * BUFB)   // double-buffered = 147456 B

// ---------------- scratch (device globals; no allocs allowed) ----------------
static __device__ float g_XM[DN * DD];
static __device__ float g_K[DN * DD];
static __device__ float g_V[DN * DD];
static __device__ float g_Q[DN * DD];
static __device__ float g_LR[DN];
static __device__ float g_Z0[DN * DD];
static __device__ float g_X1[DN * DD];
static __device__ float g_Z1[DN * DD];
static __device__ float g_X2[DN * DD];
static __device__ float g_DY2[DN * DD];
static __device__ float g_DZ1[DN * DD];
static __device__ float g_DX1[DN * DD];
static __device__ float g_DZ0[DN * DD];
static __device__ float g_Wn[NLAY * DD * DD];
static __device__ float g_W1t[DD * DD];
static __device__ float g_Y1[DN * DD];
static __device__ float g_Y2[DN * DD];
static __device__ float g_AQ[DN * DD];
static __device__ float g_AK[DN * DD];
static __device__ float g_AV[DN * DD];
static __device__ float g_AO[DN * DD];
static __device__ float g_S[DB * DH * DT * DWIN];               // banded scores/probs
static __device__ float g_GP[NLAY * NSPLIT * DD * DD];          // split-K grad partials

__device__ __forceinline__ float sigf(float z) { return 1.0f / (1.0f + __expf(-z)); }
__device__ __forceinline__ float silup(float z) {
    float s = sigf(z);
    return s * (1.0f + z * (1.0f - s));
}

// ================= warp-mma helpers (sm_80+ baseline PTX, no 'a' features) ======
__device__ __forceinline__ uint32_t smem_u32(const void* p) {
    uint32_t a;
    asm("{ .reg .u64 t; cvta.to.shared.u64 t, %1; cvt.u32.u64 %0, t; }" : "=r"(a) : "l"(p));
    return a;
}
__device__ __forceinline__ void mma16816(float* c, const uint32_t* a, const uint32_t* b) {
    asm volatile(
        "mma.sync.aligned.m16n8k16.row.col.f32.bf16.bf16.f32 "
        "{%0,%1,%2,%3}, {%4,%5,%6,%7}, {%8,%9}, {%0,%1,%2,%3};"
        : "+f"(c[0]), "+f"(c[1]), "+f"(c[2]), "+f"(c[3])
        : "r"(a[0]), "r"(a[1]), "r"(a[2]), "r"(a[3]), "r"(b[0]), "r"(b[1]));
}
__device__ __forceinline__ void ldsm4(uint32_t* r, uint32_t addr) {
    asm volatile("ldmatrix.sync.aligned.m8n8.x4.shared.b16 {%0,%1,%2,%3}, [%4];"
                 : "=r"(r[0]), "=r"(r[1]), "=r"(r[2]), "=r"(r[3]) : "r"(addr));
}
__device__ __forceinline__ void ldsm2(uint32_t* r, uint32_t addr) {
    asm volatile("ldmatrix.sync.aligned.m8n8.x2.shared.b16 {%0,%1}, [%2];"
                 : "=r"(r[0]), "=r"(r[1]) : "r"(addr));
}
// fp32 pair -> bf16x2 hi + bf16x2 lo (split-bf16)
__device__ __forceinline__ void cvt_hl(float a, float b, uint32_t& h, uint32_t& l) {
    __nv_bfloat162 th, tl;
    th.x = __float2bfloat16(a);
    th.y = __float2bfloat16(b);
    tl.x = __float2bfloat16(a - __bfloat162float(th.x));
    tl.y = __float2bfloat16(b - __bfloat162float(th.y));
    h = *reinterpret_cast<uint32_t*>(&th);
    l = *reinterpret_cast<uint32_t*>(&tl);
}

// ---- pipelined NT staging: load phase (gmem -> regs)
__device__ __forceinline__ void nt_ld(float4* r, const float* __restrict__ src,
                                      int row0, int k0, int tid) {
#pragma unroll
    for (int it = 0; it < 8; it++) {
        int idx = tid + (it << 8);            // 0..2047 float4s (128 rows x 16)
        int m = idx >> 4;
        int kq = (idx & 15) << 2;
        r[it] = *(const float4*)&src[(row0 + m) * DD + k0 + kq];
    }
}
// ---- pipelined NT staging: convert + store phase (regs -> bf16 hi/lo smem)
__device__ __forceinline__ void nt_st(char* th, char* tl, const float4* r, int tid) {
#pragma unroll
    for (int it = 0; it < 8; it++) {
        int idx = tid + (it << 8);
        int m = idx >> 4;
        int kq = (idx & 15) << 2;
        uint32_t h0, l0, h1, l1;
        cvt_hl(r[it].x, r[it].y, h0, l0);
        cvt_hl(r[it].z, r[it].w, h1, l1);
        uint32_t off = m * ROWB + (kq << 1);
        *(uint2*)(th + off) = make_uint2(h0, h1);
        *(uint2*)(tl + off) = make_uint2(l0, l1);
    }
}
// ---- staging transposed (TN mode): tile(row=i, k) = src[(kb+k)*DD + col0 + i]
__device__ __forceinline__ void stage_tn(const float* __restrict__ src, int col0, int kb,
                                         char* th, char* tl, int tid) {
    const int i = tid & 127;
    const int half = tid >> 7;                // 0,1
#pragma unroll
    for (int it = 0; it < 16; it++) {
        int k = (it << 2) + (half << 1);      // even 0..62
        float v0 = src[(kb + k) * DD + col0 + i];
        float v1 = src[(kb + k + 1) * DD + col0 + i];
        uint32_t h, l;
        cvt_hl(v0, v1, h, l);
        uint32_t off = i * ROWB + (k << 1);
        *(uint32_t*)(th + off) = h;
        *(uint32_t*)(tl + off) = l;
    }
}

// ---- mma over ks range [KS0, KS1) for the 2x4 warp grid
template <int KS0, int KS1>
__device__ __forceinline__ void mma_steps(float (&acc)[4][4][4],
                                          uint32_t aBase, uint32_t bBase) {
#pragma unroll
    for (int ks = KS0; ks < KS1; ks++) {
        const uint32_t kOff = (uint32_t)(ks << 5);   // 16 bf16 = 32B
        uint32_t ah[4][4], al[4][4], bh[4][2], bl[4][2];
#pragma unroll
        for (int mf = 0; mf < 4; mf++) {
            ldsm4(ah[mf], aBase + mf * (16 * ROWB) + kOff);
            ldsm4(al[mf], aBase + TILEB + mf * (16 * ROWB) + kOff);
        }
#pragma unroll
        for (int nf = 0; nf < 4; nf++) {
            ldsm2(bh[nf], bBase + nf * (8 * ROWB) + kOff);
            ldsm2(bl[nf], bBase + TILEB + nf * (8 * ROWB) + kOff);
        }
#pragma unroll
        for (int mf = 0; mf < 4; mf++)
#pragma unroll
            for (int nf = 0; nf < 4; nf++) {
                mma16816(acc[mf][nf], ah[mf], bh[nf]);
                mma16816(acc[mf][nf], ah[mf], bl[nf]);
                mma16816(acc[mf][nf], al[mf], bh[nf]);
            }
    }
}

// ================= 128x128 warp-mma GEMM body =================
// MODE 0 = NT (pipelined): C[M,N] = A[M,512] @ W[N,512]^T   (8 chunks of 64)
// MODE 1 = TN: C[i,j] = sum_n A[n,i] W[n,j] over split z (6 chunks of 64)
// EPI 0: Cz = z ; 1: Cz = z, Cx = A + silu(z) ; 2: d_out drop-meta ; 3: Cz = z + R
template <int MODE, int EPI>
__device__ void wm_body(const float* __restrict__ A, const float* __restrict__ W,
                        const float* __restrict__ R, float* __restrict__ Cz,
                        float* __restrict__ Cx) {
    extern __shared__ char sm[];
    const uint32_t sb = smem_u32(sm);

    const int tid = threadIdx.x;
    const int warp = tid >> 5, lane = tid & 31;
    const int wm = warp >> 2, wn = warp & 3;       // 2 x 4 warp grid
    const int m0 = blockIdx.x << 7;
    const int n0 = blockIdx.y << 7;
    const int kb0 = (MODE == 1) ? blockIdx.z * SPLITROWS : 0;
    const int NCH = (MODE == 1) ? (SPLITROWS / 64) : (DD / 64);
    float* Czp = (MODE == 1) ? (Cz + blockIdx.z * DD * DD) : Cz;

    float acc[4][4][4];
#pragma unroll
    for (int mf = 0; mf < 4; mf++)
#pragma unroll
        for (int nf = 0; nf < 4; nf++)
#pragma unroll
            for (int e = 0; e < 4; e++) acc[mf][nf][e] = 0.0f;

    // ldmatrix lane addressing (buffer-independent parts)
    const int ar = (lane & 7) + ((lane >> 3) & 1) * 8;
    const int acol = (lane >> 4) << 3;
    const int br = lane & 7;
    const int bcol = ((lane >> 3) & 1) << 3;
    const uint32_t aBase0 = sb + (wm * 64 + ar) * ROWB + acol * 2;
    const uint32_t bBase0 = sb + 2 * TILEB + (wn * 32 + br) * ROWB + bcol * 2;

    if (MODE == 0) {
        float4 pa[8], pb[8];
        // prologue: stage chunk 0 into buffer 0
        nt_ld(pa, A, m0, 0, tid);
        nt_ld(pb, W, n0, 0, tid);
        nt_st(sm, sm + TILEB, pa, tid);
        nt_st(sm + 2 * TILEB, sm + 3 * TILEB, pb, tid);
        __syncthreads();
        for (int c = 0; c < NCH; c++) {
            const uint32_t bo = (uint32_t)(c & 1) * BUFB;
            char* nb = sm + ((c & 1) ^ 1) * BUFB;
            const int k1 = (c + 1) << 6;
            if (c + 1 < NCH) nt_ld(pa, A, m0, k1, tid);
            mma_steps<0, 2>(acc, aBase0 + bo, bBase0 + bo);
            if (c + 1 < NCH) {
                nt_st(nb, nb + TILEB, pa, tid);
                nt_ld(pb, W, n0, k1, tid);
            }
            mma_steps<2, 4>(acc, aBase0 + bo, bBase0 + bo);
            if (c + 1 < NCH) nt_st(nb + 2 * TILEB, nb + 3 * TILEB, pb, tid);
            __syncthreads();
        }
    } else {
        for (int c = 0; c < NCH; c++) {
            const int k0 = kb0 + (c << 6);
            char* cb = sm + (c & 1) * BUFB;
            stage_tn(A, m0, k0, cb, cb + TILEB, tid);
            stage_tn(W, n0, k0, cb + 2 * TILEB, cb + 3 * TILEB, tid);
            __syncthreads();
            const uint32_t bo = (uint32_t)(c & 1) * BUFB;
            mma_steps<0, 4>(acc, aBase0 + bo, bBase0 + bo);
            __syncthreads();
        }
    }

    const int erow = (lane >> 2);
    const int ecol = (lane & 3) << 1;
#pragma unroll
    for (int mf = 0; mf < 4; mf++)
#pragma unroll
        for (int nf = 0; nf < 4; nf++) {
            const int colg = n0 + wn * 32 + nf * 8 + ecol;
#pragma unroll
            for (int h = 0; h < 2; h++) {
                const int rowg = m0 + wm * 64 + mf * 16 + erow + h * 8;
                float zx = acc[mf][nf][2 * h];
                float zy = acc[mf][nf][2 * h + 1];
                if (EPI == 0) {
                    *(float2*)&Czp[rowg * DD + colg] = make_float2(zx, zy);
                } else if (EPI == 1) {
                    *(float2*)&Czp[rowg * DD + colg] = make_float2(zx, zy);
                    float2 a = *(const float2*)&A[rowg * DD + colg];
                    *(float2*)&Cx[rowg * DD + colg] =
                        make_float2(a.x + zx * sigf(zx), a.y + zy * sigf(zy));
                } else if (EPI == 3) {
                    float2 r = *(const float2*)&R[rowg * DD + colg];
                    *(float2*)&Czp[rowg * DD + colg] = make_float2(zx + r.x, zy + r.y);
                } else {
                    const int bb = rowg / DT, t = rowg - bb * DT;
                    if (t >= DM)
                        *(float2*)&Cx[(bb * DS + (t - DM)) * DD + colg] = make_float2(zx, zy);
                }
            }
        }
}

template <int MODE, int EPI>
__global__ void __launch_bounds__(256, 1) wm_gemm_k(
    const float* __restrict__ A, const float* __restrict__ W,
    const float* __restrict__ R, float* __restrict__ Cz, float* __restrict__ Cx) {
    wm_body<MODE, EPI>(A, W, R, Cz, Cx);
}

__global__ void __launch_bounds__(256, 1) wm_nt3_k(
    const float* __restrict__ A,
    const float* __restrict__ W0, const float* __restrict__ W1, const float* __restrict__ W2,
    float* __restrict__ C0, float* __restrict__ C1, float* __restrict__ C2) {
    const float* W = (blockIdx.z == 0) ? W0 : (blockIdx.z == 1 ? W1 : W2);
    float* C = (blockIdx.z == 0) ? C0 : (blockIdx.z == 1 ? C1 : C2);
    wm_body<0, 0>(A, W, nullptr, C, nullptr);
}

// ---------------- 512x512 transpose (for NN -> NT) ----------------
__global__ void transpose_k(const float* __restrict__ in, float* __restrict__ outp) {
    __shared__ float t[32][33];
    int x = blockIdx.x * 32 + threadIdx.x;
    int y = blockIdx.y * 32 + threadIdx.y;
#pragma unroll
    for (int j = 0; j < 32; j += 8) t[threadIdx.y + j][threadIdx.x] = in[(y + j) * DD + x];
    __syncthreads();
    x = blockIdx.y * 32 + threadIdx.x;
    y = blockIdx.x * 32 + threadIdx.y;
#pragma unroll
    for (int j = 0; j < 32; j += 8) outp[(y + j) * DD + x] = t[threadIdx.x][threadIdx.y + j];
}

// ---------------- build xm = concat(meta, x) ----------------
__global__ void build_xm_k(const float* __restrict__ x, const float* __restrict__ meta,
                           float* __restrict__ XM) {
    int idx = blockIdx.x * blockDim.x + threadIdx.x;
    if (idx >= DN * DD / 4) return;
    int e = idx << 2;
    int n = e / DD, d = e - n * DD;
    int b = n / DT, t = n - b * DT;
    float4 v;
    if (t < DM) v = *(const float4*)&meta[t * DD + d];
    else        v = *(const float4*)&x[(b * DS + (t - DM)) * DD + d];
    *(float4*)&XM[e] = v;
}

// ---------------- adaptive lr ----------------
__global__ void lr_proj_k(const float* __restrict__ XM, const float* __restrict__ wlr,
                          float* __restrict__ out) {
    int warp = (blockIdx.x * blockDim.x + threadIdx.x) >> 5;
    int lane = threadIdx.x & 31;
    if (warp >= DN) return;
    const float* xr = XM + warp * DD;
    float s = 0.0f;
#pragma unroll
    for (int i = 0; i < DD / 32; i++) s = fmaf(xr[lane + i * 32], wlr[lane + i * 32], s);
#pragma unroll
    for (int o = 16; o > 0; o >>= 1) s += __shfl_xor_sync(0xffffffffu, s, o);
    if (lane == 0) out[warp] = MAXALR * sigf(s);
}

// ---------------- head gradient + layer1 act backward ----------------
__global__ void grad_head_k(const float* __restrict__ X2, const float* __restrict__ Vv,
                            const float* __restrict__ Z1, const float* __restrict__ LRv,
                            float* __restrict__ DY2, float* __restrict__ DZ1) {
    int i = blockIdx.x * blockDim.x + threadIdx.x;
    if (i >= DN * DD) return;
    int n = i >> 9;
    float c = (2.0f / (float)DD) * LRv[n];
    float d2 = c * (X2[i] - Vv[i]);
    DY2[i] = d2;
    DZ1[i] = d2 * silup(Z1[i]);
}

__global__ void bwd_act0_k(const float* __restrict__ DX1, const float* __restrict__ Z0,
                           float* __restrict__ DZ0) {
    int i = blockIdx.x * blockDim.x + threadIdx.x;
    if (i >= DN * DD) return;
    DZ0[i] = DX1[i] * silup(Z0[i]);
}

// ---------------- reduce split-K partials + AdamW ----------------
__global__ void adamw_k(const float* __restrict__ W, float* __restrict__ Wn) {
    int idx = blockIdx.x * blockDim.x + threadIdx.x;
    if (idx >= NLAY * DD * DD) return;
    int l = idx / (DD * DD);
    int e = idx - l * (DD * DD);
    const float* gp = g_GP + l * NSPLIT * DD * DD;
    float g = 0.0f;
#pragma unroll
    for (int s = 0; s < NSPLIT; s++) g += gp[s * DD * DD + e];
    g *= (1.0f / 16.0f);
    float w = W[idx];
    Wn[idx] = w * (1.0f - LRC * WDC) - LRC * g / (fabsf(g) + EPSC);
}

#define FMA4x4(a, bb) do { \
    acc[0][0] = fmaf(a.x, bb.x, acc[0][0]); acc[0][1] = fmaf(a.x, bb.y, acc[0][1]); \
    acc[0][2] = fmaf(a.x, bb.z, acc[0][2]); acc[0][3] = fmaf(a.x, bb.w, acc[0][3]); \
    acc[1][0] = fmaf(a.y, bb.x, acc[1][0]); acc[1][1] = fmaf(a.y, bb.y, acc[1][1]); \
    acc[1][2] = fmaf(a.y, bb.z, acc[1][2]); acc[1][3] = fmaf(a.y, bb.w, acc[1][3]); \
    acc[2][0] = fmaf(a.z, bb.x, acc[2][0]); acc[2][1] = fmaf(a.z, bb.y, acc[2][1]); \
    acc[2][2] = fmaf(a.z, bb.z, acc[2][2]); acc[2][3] = fmaf(a.z, bb.w, acc[2][3]); \
    acc[3][0] = fmaf(a.w, bb.x, acc[3][0]); acc[3][1] = fmaf(a.w, bb.y, acc[3][1]); \
    acc[3][2] = fmaf(a.w, bb.z, acc[3][2]); acc[3][3] = fmaf(a.w, bb.w, acc[3][3]); \
} while (0)

// ---------------- attention: banded scores (SIMT, known good) ----------------
__global__ void __launch_bounds__(256, 2) attn_scores_k(
    const float* __restrict__ AQ, const float* __restrict__ AK, float* __restrict__ Sb) {
    __shared__ __align__(16) float Qs[64][68];
    __shared__ __align__(16) float Ks[64][68];
    const int q0 = blockIdx.x << 6;
    const int h = blockIdx.y, b = blockIdx.z;
    const int tid = threadIdx.x;
    const int tx = tid & 15, ty = tid >> 4;
#pragma unroll
    for (int i = 0; i < 4; i++) {
        int idx = tid + (i << 8);
        int r = idx >> 4, c4 = (idx & 15) << 2;
        float4 v = *(const float4*)&AQ[(b * DT + q0 + r) * DD + h * DHD + c4];
        Qs[c4 + 0][r] = v.x; Qs[c4 + 1][r] = v.y; Qs[c4 + 2][r] = v.z; Qs[c4 + 3][r] = v.w;
    }
    __syncthreads();
    int kLo = q0 - (DWIN - 1);
    if (kLo < 0) kLo = 0;
    kLo &= ~63;
    for (int k0 = kLo; k0 <= q0 + 63; k0 += 64) {
#pragma unroll
        for (int i = 0; i < 4; i++) {
            int idx = tid + (i << 8);
            int r = idx >> 4, c4 = (idx & 15) << 2;
            int k = k0 + r;
            float4 v = make_float4(0.f, 0.f, 0.f, 0.f);
            if (k < DT) v = *(const float4*)&AK[(b * DT + k) * DD + h * DHD + c4];
            Ks[c4 + 0][r] = v.x; Ks[c4 + 1][r] = v.y; Ks[c4 + 2][r] = v.z; Ks[c4 + 3][r] = v.w;
        }
        __syncthreads();
        float acc[4][4] = {};
#pragma unroll 16
        for (int cc = 0; cc < 64; cc++) {
            float4 a = *(const float4*)&Qs[cc][tx << 2];
            float4 bb = *(const float4*)&Ks[cc][ty << 2];
            FMA4x4(a, bb);
        }
#pragma unroll
        for (int i = 0; i < 4; i++)
#pragma unroll
            for (int j = 0; j < 4; j++) {
                int q = q0 + (tx << 2) + i;
                int k = k0 + (ty << 2) + j;
                if (k <= q && q - k < DWIN)
                    Sb[((size_t)(b * DH + h) * DT + q) * DWIN + (k - q + DWIN - 1)] = acc[i][j] * 0.125f;
            }
        __syncthreads();
    }
}

// ---------------- attention: softmax over band ----------------
__global__ void attn_softmax_k(float* __restrict__ Sb) {
    int gw = (blockIdx.x * blockDim.x + threadIdx.x) >> 5;
    int lane = threadIdx.x & 31;
    if (gw >= DB * DH * DT) return;
    int q = gw % DT;
    int wlo = DWIN - 1 - q;
    if (wlo < 0) wlo = 0;
    float* row = Sb + (size_t)gw * DWIN;
    float v[16];
    float m = -1e30f;
#pragma unroll
    for (int i = 0; i < 16; i++) {
        int w = lane + i * 32;
        v[i] = (w >= wlo) ? row[w] : -1e30f;
        m = fmaxf(m, v[i]);
    }
#pragma unroll
    for (int o = 16; o > 0; o >>= 1) m = fmaxf(m, __shfl_xor_sync(0xffffffffu, m, o));
    float sum = 0.0f;
#pragma unroll
    for (int i = 0; i < 16; i++) {
        int w = lane + i * 32;
        v[i] = (w >= wlo) ? __expf(v[i] - m) : 0.0f;
        sum += v[i];
    }
#pragma unroll
    for (int o = 16; o > 0; o >>= 1) sum += __shfl_xor_sync(0xffffffffu, sum, o);
    float inv = 1.0f / sum;
#pragma unroll
    for (int i = 0; i < 16; i++) {
        int w = lane + i * 32;
        if (w >= wlo) row[w] = v[i] * inv;
    }
}

// ---------------- attention: P @ V (SIMT, known good) ----------------
__global__ void __launch_bounds__(256, 2) attn_pv_k(
    const float* __restrict__ Sb, const float* __restrict__ AV, float* __restrict__ AO) {
    __shared__ __align__(16) float Ps[64][68];
    __shared__ __align__(16) float Vs[64][68];
    const int q0 = blockIdx.x << 6;
    const int h = blockIdx.y, b = blockIdx.z;
    const int tid = threadIdx.x;
    const int tx = tid & 15, ty = tid >> 4;
    float acc[4][4] = {};
    int kLo = q0 - (DWIN - 1);
    if (kLo < 0) kLo = 0;
    kLo &= ~63;
    for (int k0 = kLo; k0 <= q0 + 63; k0 += 64) {
#pragma unroll
        for (int i = 0; i < 4; i++) {
            int idx = tid + (i << 8);
            int r = idx >> 4, c4 = (idx & 15) << 2;
            int k = k0 + r;
            float4 v = make_float4(0.f, 0.f, 0.f, 0.f);
            if (k < DT) v = *(const float4*)&AV[(b * DT + k) * DD + h * DHD + c4];
            *(float4*)&Vs[r][c4] = v;
        }
#pragma unroll
        for (int i = 0; i < 16; i++) {
            int lin = tid + (i << 8);
            int qi = lin >> 6, kj = lin & 63;
            int q = q0 + qi, k = k0 + kj;
            float p = 0.0f;
            if (k <= q && q - k < DWIN)
                p = Sb[((size_t)(b * DH + h) * DT + q) * DWIN + (k - q + DWIN - 1)];
            Ps[kj][qi] = p;
        }
        __syncthreads();
#pragma unroll 16
        for (int kk = 0; kk < 64; kk++) {
            float4 a = *(const float4*)&Ps[kk][tx << 2];
            float4 bb = *(const float4*)&Vs[kk][ty << 2];
            FMA4x4(a, bb);
        }
        __syncthreads();
    }
#pragma unroll
    for (int i = 0; i < 4; i++)
#pragma unroll
        for (int j = 0; j < 4; j++)
            AO[(size_t)(b * DT + q0 + (tx << 2) + i) * DD + h * DHD + (ty << 2) + j] = acc[i][j];
}

// ---------------- host ----------------
extern "C" void kernel_launch(void* const* d_in, const int* in_sizes, int n_in,
                              void* d_out, int out_size) {
    const float* x      = (const float*)d_in[0];
    const float* meta   = (const float*)d_in[1];
    const float* lmm_w  = (const float*)d_in[2];
    const float* w_q    = (const float*)d_in[3];
    const float* w_k    = (const float*)d_in[4];
    const float* w_v    = (const float*)d_in[5];
    const float* w_lr   = (const float*)d_in[6];
    const float* swa_wq = (const float*)d_in[7];
    const float* swa_wk = (const float*)d_in[8];
    const float* swa_wv = (const float*)d_in[9];
    const float* swa_wo = (const float*)d_in[10];
    float* out = (float*)d_out;

    float *XM, *K, *V, *Q, *LR, *Z0, *X1, *Z1, *X2, *DY2, *DZ1, *DX1, *DZ0;
    float *Wn, *W1t, *Y1, *Y2, *AQ, *AK, *AV, *AO, *Sb, *GP;
    cudaGetSymbolAddress((void**)&XM, g_XM);
    cudaGetSymbolAddress((void**)&K, g_K);
    cudaGetSymbolAddress((void**)&V, g_V);
    cudaGetSymbolAddress((void**)&Q, g_Q);
    cudaGetSymbolAddress((void**)&LR, g_LR);
    cudaGetSymbolAddress((void**)&Z0, g_Z0);
    cudaGetSymbolAddress((void**)&X1, g_X1);
    cudaGetSymbolAddress((void**)&Z1, g_Z1);
    cudaGetSymbolAddress((void**)&X2, g_X2);
    cudaGetSymbolAddress((void**)&DY2, g_DY2);
    cudaGetSymbolAddress((void**)&DZ1, g_DZ1);
    cudaGetSymbolAddress((void**)&DX1, g_DX1);
    cudaGetSymbolAddress((void**)&DZ0, g_DZ0);
    cudaGetSymbolAddress((void**)&Wn, g_Wn);
    cudaGetSymbolAddress((void**)&W1t, g_W1t);
    cudaGetSymbolAddress((void**)&Y1, g_Y1);
    cudaGetSymbolAddress((void**)&Y2, g_Y2);
    cudaGetSymbolAddress((void**)&AQ, g_AQ);
    cudaGetSymbolAddress((void**)&AK, g_AK);
    cudaGetSymbolAddress((void**)&AV, g_AV);
    cudaGetSymbolAddress((void**)&AO, g_AO);
    cudaGetSymbolAddress((void**)&Sb, g_S);
    cudaGetSymbolAddress((void**)&GP, g_GP);

    cudaFuncSetAttribute(wm_nt3_k, cudaFuncAttributeMaxDynamicSharedMemorySize, WM_SMEM);
    cudaFuncSetAttribute(wm_gemm_k<0, 1>, cudaFuncAttributeMaxDynamicSharedMemorySize, WM_SMEM);
    cudaFuncSetAttribute(wm_gemm_k<0, 2>, cudaFuncAttributeMaxDynamicSharedMemorySize, WM_SMEM);
    cudaFuncSetAttribute(wm_gemm_k<0, 3>, cudaFuncAttributeMaxDynamicSharedMemorySize, WM_SMEM);
    cudaFuncSetAttribute(wm_gemm_k<1, 0>, cudaFuncAttributeMaxDynamicSharedMemorySize, WM_SMEM);

    const dim3 gG(DN / 128, DD / 128);          // 33 x 4
    const dim3 gG3(DN / 128, DD / 128, 3);      // batched projections
    const dim3 gTN(DD / 128, DD / 128, NSPLIT); // 4 x 4 x 11
    const dim3 gAT(DT / 64, DH, DB);            // 33 x 8 x 2
    const int EW = (DN * DD + 255) / 256;

    // 1. concat meta + x ; transpose W1 for the NN gemm
    build_xm_k<<<(DN * DD / 4 + 255) / 256, 256>>>(x, meta, XM);
    transpose_k<<<dim3(16, 16), dim3(32, 8)>>>(lmm_w + DD * DD, W1t);
    // 2. projections (K, V, Q batched)
    wm_nt3_k<<<gG3, 256, WM_SMEM>>>(XM, w_k, w_v, w_q, K, V, Q);
    lr_proj_k<<<(DN * 32 + 255) / 256, 256>>>(XM, w_lr, LR);
    // 3. LMM forward on keys
    wm_gemm_k<0, 1><<<gG, 256, WM_SMEM>>>(K, lmm_w, nullptr, Z0, X1);
    wm_gemm_k<0, 1><<<gG, 256, WM_SMEM>>>(X1, lmm_w + DD * DD, nullptr, Z1, X2);
    // 4. backward
    grad_head_k<<<EW, 256>>>(X2, V, Z1, LR, DY2, DZ1);
    wm_gemm_k<1, 0><<<gTN, 256, WM_SMEM>>>(DZ1, X1, nullptr, GP + NSPLIT * DD * DD, nullptr); // dW1
    wm_gemm_k<0, 3><<<gG, 256, WM_SMEM>>>(DZ1, W1t, DY2, DX1, nullptr);                       // dx1
    bwd_act0_k<<<EW, 256>>>(DX1, Z0, DZ0);
    wm_gemm_k<1, 0><<<gTN, 256, WM_SMEM>>>(DZ0, K, nullptr, GP, nullptr);                     // dW0
    // 5. AdamW first step
    adamw_k<<<(NLAY * DD * DD + 255) / 256, 256>>>(lmm_w, Wn);
    // 6. retrieval with updated weights
    wm_gemm_k<0, 1><<<gG, 256, WM_SMEM>>>(Q, Wn, nullptr, Z0, Y1);
    wm_gemm_k<0, 1><<<gG, 256, WM_SMEM>>>(Y1, Wn + DD * DD, nullptr, Z1, Y2);
    // 7. sliding-window attention (SIMT, known good)
    wm_nt3_k<<<gG3, 256, WM_SMEM>>>(Y2, swa_wq, swa_wk, swa_wv, AQ, AK, AV);
    attn_scores_k<<<gAT, 256>>>(AQ, AK, Sb);
    attn_softmax_k<<<(DB * DH * DT * 32 + 255) / 256, 256>>>(Sb);
    attn_pv_k<<<gAT, 256>>>(Sb, AV, AO);
    // 8. output projection, dropping meta rows
    wm_gemm_k<0, 2><<<gG, 256, WM_SMEM>>>(AO, swa_wo, nullptr, nullptr, out);
}

// round 13
// speedup vs baseline: 1.3552x; 1.0757x over previous
#include <cuda_runtime.h>
#include <cuda_bf16.h>
#include <cstdint>

// ---------------- problem constants ----------------
#define DB 2
#define DS 2048
#define DD 512
#define DM 64
#define DT 2112              // DM + DS
#define DN 4224              // DB * DT
#define DH 8
#define DHD 64
#define DWIN 512
#define NSPLIT 11
#define SPLITROWS 384        // DN / NSPLIT = 384 (6 chunks of 64)
#define NLAY 2
#define LRC 1e-3f
#define WDC 1e-2f
#define EPSC 1e-8f
#define MAXALR 0.01f

// warp-mma tile constants
#define ROWB 144             // bytes per smem tile row (64 bf16 = 128B + 16B pad)
#define TILEB (128 * ROWB)   // 18432 B per tile
#define BUFB (4 * TILEB)     // Ah, Al, Bh, Bl = 73728 B per buffer
#define WM_SMEM (2 * BUFB)   // double-buffered = 147456 B

// fused attention smem layout (bytes); tiles are [64][68] floats
#define AT_TILE (64 * 68 * 4)          // 17408
#define AT_QS 0
#define AT_KS (AT_TILE)
#define AT_PS (2 * AT_TILE)
#define AT_VS (3 * AT_TILE)
#define AT_RED (4 * AT_TILE)           // 16 x 64 floats = 4096
#define AT_MROW (AT_RED + 4096)        // 64 floats
#define AT_LROW (AT_MROW + 256)
#define AT_CROW (AT_LROW + 256)
#define AT_SMEM (AT_CROW + 256)        // 74496

// ---------------- scratch (device globals; no allocs allowed) ----------------
static __device__ float g_XM[DN * DD];
static __device__ float g_K[DN * DD];
static __device__ float g_V[DN * DD];
static __device__ float g_Q[DN * DD];
static __device__ float g_LR[DN];
static __device__ float g_Z0[DN * DD];
static __device__ float g_X1[DN * DD];
static __device__ float g_Z1[DN * DD];
static __device__ float g_X2[DN * DD];
static __device__ float g_DY2[DN * DD];
static __device__ float g_DZ1[DN * DD];
static __device__ float g_DX1[DN * DD];
static __device__ float g_DZ0[DN * DD];
static __device__ float g_Wn[NLAY * DD * DD];
static __device__ float g_W1t[DD * DD];
static __device__ float g_Y1[DN * DD];
static __device__ float g_Y2[DN * DD];
static __device__ float g_AQ[DN * DD];
static __device__ float g_AK[DN * DD];
static __device__ float g_AV[DN * DD];
static __device__ float g_AO[DN * DD];
static __device__ float g_GP[NLAY * NSPLIT * DD * DD];          // split-K grad partials

__device__ __forceinline__ float sigf(float z) { return 1.0f / (1.0f + __expf(-z)); }
__device__ __forceinline__ float silup(float z) {
    float s = sigf(z);
    return s * (1.0f + z * (1.0f - s));
}

// ================= warp-mma helpers (sm_80+ baseline PTX, no 'a' features) ======
__device__ __forceinline__ uint32_t smem_u32(const void* p) {
    uint32_t a;
    asm("{ .reg .u64 t; cvta.to.shared.u64 t, %1; cvt.u32.u64 %0, t; }" : "=r"(a) : "l"(p));
    return a;
}
__device__ __forceinline__ void mma16816(float* c, const uint32_t* a, const uint32_t* b) {
    asm volatile(
        "mma.sync.aligned.m16n8k16.row.col.f32.bf16.bf16.f32 "
        "{%0,%1,%2,%3}, {%4,%5,%6,%7}, {%8,%9}, {%0,%1,%2,%3};"
        : "+f"(c[0]), "+f"(c[1]), "+f"(c[2]), "+f"(c[3])
        : "r"(a[0]), "r"(a[1]), "r"(a[2]), "r"(a[3]), "r"(b[0]), "r"(b[1]));
}
__device__ __forceinline__ void ldsm4(uint32_t* r, uint32_t addr) {
    asm volatile("ldmatrix.sync.aligned.m8n8.x4.shared.b16 {%0,%1,%2,%3}, [%4];"
                 : "=r"(r[0]), "=r"(r[1]), "=r"(r[2]), "=r"(r[3]) : "r"(addr));
}
__device__ __forceinline__ void ldsm2(uint32_t* r, uint32_t addr) {
    asm volatile("ldmatrix.sync.aligned.m8n8.x2.shared.b16 {%0,%1}, [%2];"
                 : "=r"(r[0]), "=r"(r[1]) : "r"(addr));
}
// fp32 pair -> bf16x2 hi + bf16x2 lo (split-bf16)
__device__ __forceinline__ void cvt_hl(float a, float b, uint32_t& h, uint32_t& l) {
    __nv_bfloat162 th, tl;
    th.x = __float2bfloat16(a);
    th.y = __float2bfloat16(b);
    tl.x = __float2bfloat16(a - __bfloat162float(th.x));
    tl.y = __float2bfloat16(b - __bfloat162float(th.y));
    h = *reinterpret_cast<uint32_t*>(&th);
    l = *reinterpret_cast<uint32_t*>(&tl);
}

// ---- pipelined NT staging: load phase (gmem -> regs)
__device__ __forceinline__ void nt_ld(float4* r, const float* __restrict__ src,
                                      int row0, int k0, int tid) {
#pragma unroll
    for (int it = 0; it < 8; it++) {
        int idx = tid + (it << 8);            // 0..2047 float4s (128 rows x 16)
        int m = idx >> 4;
        int kq = (idx & 15) << 2;
        r[it] = *(const float4*)&src[(row0 + m) * DD + k0 + kq];
    }
}
// ---- pipelined NT staging: convert + store phase (regs -> bf16 hi/lo smem)
__device__ __forceinline__ void nt_st(char* th, char* tl, const float4* r, int tid) {
#pragma unroll
    for (int it = 0; it < 8; it++) {
        int idx = tid + (it << 8);
        int m = idx >> 4;
        int kq = (idx & 15) << 2;
        uint32_t h0, l0, h1, l1;
        cvt_hl(r[it].x, r[it].y, h0, l0);
        cvt_hl(r[it].z, r[it].w, h1, l1);
        uint32_t off = m * ROWB + (kq << 1);
        *(uint2*)(th + off) = make_uint2(h0, h1);
        *(uint2*)(tl + off) = make_uint2(l0, l1);
    }
}
// ---- staging transposed (TN mode): tile(row=i, k) = src[(kb+k)*DD + col0 + i]
__device__ __forceinline__ void stage_tn(const float* __restrict__ src, int col0, int kb,
                                         char* th, char* tl, int tid) {
    const int i = tid & 127;
    const int half = tid >> 7;                // 0,1
#pragma unroll
    for (int it = 0; it < 16; it++) {
        int k = (it << 2) + (half << 1);      // even 0..62
        float v0 = src[(kb + k) * DD + col0 + i];
        float v1 = src[(kb + k + 1) * DD + col0 + i];
        uint32_t h, l;
        cvt_hl(v0, v1, h, l);
        uint32_t off = i * ROWB + (k << 1);
        *(uint32_t*)(th + off) = h;
        *(uint32_t*)(tl + off) = l;
    }
}

// ---- mma over ks range [KS0, KS1) for the 2x4 warp grid
template <int KS0, int KS1>
__device__ __forceinline__ void mma_steps(float (&acc)[4][4][4],
                                          uint32_t aBase, uint32_t bBase) {
#pragma unroll
    for (int ks = KS0; ks < KS1; ks++) {
        const uint32_t kOff = (uint32_t)(ks << 5);   // 16 bf16 = 32B
        uint32_t ah[4][4], al[4][4], bh[4][2], bl[4][2];
#pragma unroll
        for (int mf = 0; mf < 4; mf++) {
            ldsm4(ah[mf], aBase + mf * (16 * ROWB) + kOff);
            ldsm4(al[mf], aBase + TILEB + mf * (16 * ROWB) + kOff);
        }
#pragma unroll
        for (int nf = 0; nf < 4; nf++) {
            ldsm2(bh[nf], bBase + nf * (8 * ROWB) + kOff);
            ldsm2(bl[nf], bBase + TILEB + nf * (8 * ROWB) + kOff);
        }
#pragma unroll
        for (int mf = 0; mf < 4; mf++)
#pragma unroll
            for (int nf = 0; nf < 4; nf++) {
                mma16816(acc[mf][nf], ah[mf], bh[nf]);
                mma16816(acc[mf][nf], ah[mf], bl[nf]);
                mma16816(acc[mf][nf], al[mf], bh[nf]);
            }
    }
}

// ================= 128x128 warp-mma GEMM body =================
// MODE 0 = NT (pipelined): C[M,N] = A[M,512] @ W[N,512]^T   (8 chunks of 64)
// MODE 1 = TN: C[i,j] = sum_n A[n,i] W[n,j] over split z (6 chunks of 64)
// EPI 0: Cz = z ; 1: Cz = z, Cx = A + silu(z) ; 2: d_out drop-meta ; 3: Cz = z + R
template <int MODE, int EPI>
__device__ void wm_body(const float* __restrict__ A, const float* __restrict__ W,
                        const float* __restrict__ R, float* __restrict__ Cz,
                        float* __restrict__ Cx) {
    extern __shared__ char sm[];
    const uint32_t sb = smem_u32(sm);

    const int tid = threadIdx.x;
    const int warp = tid >> 5, lane = tid & 31;
    const int wm = warp >> 2, wn = warp & 3;       // 2 x 4 warp grid
    const int m0 = blockIdx.x << 7;
    const int n0 = blockIdx.y << 7;
    const int kb0 = (MODE == 1) ? blockIdx.z * SPLITROWS : 0;
    const int NCH = (MODE == 1) ? (SPLITROWS / 64) : (DD / 64);
    float* Czp = (MODE == 1) ? (Cz + blockIdx.z * DD * DD) : Cz;

    float acc[4][4][4];
#pragma unroll
    for (int mf = 0; mf < 4; mf++)
#pragma unroll
        for (int nf = 0; nf < 4; nf++)
#pragma unroll
            for (int e = 0; e < 4; e++) acc[mf][nf][e] = 0.0f;

    const int ar = (lane & 7) + ((lane >> 3) & 1) * 8;
    const int acol = (lane >> 4) << 3;
    const int br = lane & 7;
    const int bcol = ((lane >> 3) & 1) << 3;
    const uint32_t aBase0 = sb + (wm * 64 + ar) * ROWB + acol * 2;
    const uint32_t bBase0 = sb + 2 * TILEB + (wn * 32 + br) * ROWB + bcol * 2;

    if (MODE == 0) {
        float4 pa[8], pb[8];
        nt_ld(pa, A, m0, 0, tid);
        nt_ld(pb, W, n0, 0, tid);
        nt_st(sm, sm + TILEB, pa, tid);
        nt_st(sm + 2 * TILEB, sm + 3 * TILEB, pb, tid);
        __syncthreads();
        for (int c = 0; c < NCH; c++) {
            const uint32_t bo = (uint32_t)(c & 1) * BUFB;
            char* nb = sm + ((c & 1) ^ 1) * BUFB;
            const int k1 = (c + 1) << 6;
            if (c + 1 < NCH) nt_ld(pa, A, m0, k1, tid);
            mma_steps<0, 2>(acc, aBase0 + bo, bBase0 + bo);
            if (c + 1 < NCH) {
                nt_st(nb, nb + TILEB, pa, tid);
                nt_ld(pb, W, n0, k1, tid);
            }
            mma_steps<2, 4>(acc, aBase0 + bo, bBase0 + bo);
            if (c + 1 < NCH) nt_st(nb + 2 * TILEB, nb + 3 * TILEB, pb, tid);
            __syncthreads();
        }
    } else {
        for (int c = 0; c < NCH; c++) {
            const int k0 = kb0 + (c << 6);
            char* cb = sm + (c & 1) * BUFB;
            stage_tn(A, m0, k0, cb, cb + TILEB, tid);
            stage_tn(W, n0, k0, cb + 2 * TILEB, cb + 3 * TILEB, tid);
            __syncthreads();
            const uint32_t bo = (uint32_t)(c & 1) * BUFB;
            mma_steps<0, 4>(acc, aBase0 + bo, bBase0 + bo);
            __syncthreads();
        }
    }

    const int erow = (lane >> 2);
    const int ecol = (lane & 3) << 1;
#pragma unroll
    for (int mf = 0; mf < 4; mf++)
#pragma unroll
        for (int nf = 0; nf < 4; nf++) {
            const int colg = n0 + wn * 32 + nf * 8 + ecol;
#pragma unroll
            for (int h = 0; h < 2; h++) {
                const int rowg = m0 + wm * 64 + mf * 16 + erow + h * 8;
                float zx = acc[mf][nf][2 * h];
                float zy = acc[mf][nf][2 * h + 1];
                if (EPI == 0) {
                    *(float2*)&Czp[rowg * DD + colg] = make_float2(zx, zy);
                } else if (EPI == 1) {
                    *(float2*)&Czp[rowg * DD + colg] = make_float2(zx, zy);
                    float2 a = *(const float2*)&A[rowg * DD + colg];
                    *(float2*)&Cx[rowg * DD + colg] =
                        make_float2(a.x + zx * sigf(zx), a.y + zy * sigf(zy));
                } else if (EPI == 3) {
                    float2 r = *(const float2*)&R[rowg * DD + colg];
                    *(float2*)&Czp[rowg * DD + colg] = make_float2(zx + r.x, zy + r.y);
                } else {
                    const int bb = rowg / DT, t = rowg - bb * DT;
                    if (t >= DM)
                        *(float2*)&Cx[(bb * DS + (t - DM)) * DD + colg] = make_float2(zx, zy);
                }
            }
        }
}

template <int MODE, int EPI>
__global__ void __launch_bounds__(256, 1) wm_gemm_k(
    const float* __restrict__ A, const float* __restrict__ W,
    const float* __restrict__ R, float* __restrict__ Cz, float* __restrict__ Cx) {
    wm_body<MODE, EPI>(A, W, R, Cz, Cx);
}

__global__ void __launch_bounds__(256, 1) wm_nt3_k(
    const float* __restrict__ A,
    const float* __restrict__ W0, const float* __restrict__ W1, const float* __restrict__ W2,
    float* __restrict__ C0, float* __restrict__ C1, float* __restrict__ C2) {
    const float* W = (blockIdx.z == 0) ? W0 : (blockIdx.z == 1 ? W1 : W2);
    float* C = (blockIdx.z == 0) ? C0 : (blockIdx.z == 1 ? C1 : C2);
    wm_body<0, 0>(A, W, nullptr, C, nullptr);
}

// ---------------- 512x512 transpose (for NN -> NT) ----------------
__global__ void transpose_k(const float* __restrict__ in, float* __restrict__ outp) {
    __shared__ float t[32][33];
    int x = blockIdx.x * 32 + threadIdx.x;
    int y = blockIdx.y * 32 + threadIdx.y;
#pragma unroll
    for (int j = 0; j < 32; j += 8) t[threadIdx.y + j][threadIdx.x] = in[(y + j) * DD + x];
    __syncthreads();
    x = blockIdx.y * 32 + threadIdx.x;
    y = blockIdx.x * 32 + threadIdx.y;
#pragma unroll
    for (int j = 0; j < 32; j += 8) outp[(y + j) * DD + x] = t[threadIdx.x][threadIdx.y + j];
}

// ---------------- build xm = concat(meta, x) ----------------
__global__ void build_xm_k(const float* __restrict__ x, const float* __restrict__ meta,
                           float* __restrict__ XM) {
    int idx = blockIdx.x * blockDim.x + threadIdx.x;
    if (idx >= DN * DD / 4) return;
    int e = idx << 2;
    int n = e / DD, d = e - n * DD;
    int b = n / DT, t = n - b * DT;
    float4 v;
    if (t < DM) v = *(const float4*)&meta[t * DD + d];
    else        v = *(const float4*)&x[(b * DS + (t - DM)) * DD + d];
    *(float4*)&XM[e] = v;
}

// ---------------- adaptive lr ----------------
__global__ void lr_proj_k(const float* __restrict__ XM, const float* __restrict__ wlr,
                          float* __restrict__ out) {
    int warp = (blockIdx.x * blockDim.x + threadIdx.x) >> 5;
    int lane = threadIdx.x & 31;
    if (warp >= DN) return;
    const float* xr = XM + warp * DD;
    float s = 0.0f;
#pragma unroll
    for (int i = 0; i < DD / 32; i++) s = fmaf(xr[lane + i * 32], wlr[lane + i * 32], s);
#pragma unroll
    for (int o = 16; o > 0; o >>= 1) s += __shfl_xor_sync(0xffffffffu, s, o);
    if (lane == 0) out[warp] = MAXALR * sigf(s);
}

// ---------------- head gradient + layer1 act backward ----------------
__global__ void grad_head_k(const float* __restrict__ X2, const float* __restrict__ Vv,
                            const float* __restrict__ Z1, const float* __restrict__ LRv,
                            float* __restrict__ DY2, float* __restrict__ DZ1) {
    int i = blockIdx.x * blockDim.x + threadIdx.x;
    if (i >= DN * DD) return;
    int n = i >> 9;
    float c = (2.0f / (float)DD) * LRv[n];
    float d2 = c * (X2[i] - Vv[i]);
    DY2[i] = d2;
    DZ1[i] = d2 * silup(Z1[i]);
}

__global__ void bwd_act0_k(const float* __restrict__ DX1, const float* __restrict__ Z0,
                           float* __restrict__ DZ0) {
    int i = blockIdx.x * blockDim.x + threadIdx.x;
    if (i >= DN * DD) return;
    DZ0[i] = DX1[i] * silup(Z0[i]);
}

// ---------------- reduce split-K partials + AdamW ----------------
__global__ void adamw_k(const float* __restrict__ W, float* __restrict__ Wn) {
    int idx = blockIdx.x * blockDim.x + threadIdx.x;
    if (idx >= NLAY * DD * DD) return;
    int l = idx / (DD * DD);
    int e = idx - l * (DD * DD);
    const float* gp = g_GP + l * NSPLIT * DD * DD;
    float g = 0.0f;
#pragma unroll
    for (int s = 0; s < NSPLIT; s++) g += gp[s * DD * DD + e];
    g *= (1.0f / 16.0f);
    float w = W[idx];
    Wn[idx] = w * (1.0f - LRC * WDC) - LRC * g / (fabsf(g) + EPSC);
}

#define FMA4x4(a, bb) do { \
    acc[0][0] = fmaf(a.x, bb.x, acc[0][0]); acc[0][1] = fmaf(a.x, bb.y, acc[0][1]); \
    acc[0][2] = fmaf(a.x, bb.z, acc[0][2]); acc[0][3] = fmaf(a.x, bb.w, acc[0][3]); \
    acc[1][0] = fmaf(a.y, bb.x, acc[1][0]); acc[1][1] = fmaf(a.y, bb.y, acc[1][1]); \
    acc[1][2] = fmaf(a.y, bb.z, acc[1][2]); acc[1][3] = fmaf(a.y, bb.w, acc[1][3]); \
    acc[2][0] = fmaf(a.z, bb.x, acc[2][0]); acc[2][1] = fmaf(a.z, bb.y, acc[2][1]); \
    acc[2][2] = fmaf(a.z, bb.z, acc[2][2]); acc[2][3] = fmaf(a.z, bb.w, acc[2][3]); \
    acc[3][0] = fmaf(a.w, bb.x, acc[3][0]); acc[3][1] = fmaf(a.w, bb.y, acc[3][1]); \
    acc[3][2] = fmaf(a.w, bb.z, acc[3][2]); acc[3][3] = fmaf(a.w, bb.w, acc[3][3]); \
} while (0)

// ================ fused flash-style sliding-window attention ================
// One CTA = 64 q rows of one (b, h). Online softmax; no score buffer.
__global__ void __launch_bounds__(256, 2) attn_fused_k(
    const float* __restrict__ AQ, const float* __restrict__ AK,
    const float* __restrict__ AV, float* __restrict__ AO) {
    extern __shared__ char asm_[];
    float* Qs = (float*)(asm_ + AT_QS);     // [64][68]  (c-major: Qs[c][q])
    float* Ks = (float*)(asm_ + AT_KS);     // [64][68]  (Ks[c][k])
    float* Ps = (float*)(asm_ + AT_PS);     // [64][68]  (Ps[k][q])
    float* Vs = (float*)(asm_ + AT_VS);     // [64][68]  (Vs[k][d])
    float* red = (float*)(asm_ + AT_RED);   // [16][64]
    float* mrow = (float*)(asm_ + AT_MROW); // [64]
    float* lrow = (float*)(asm_ + AT_LROW); // [64]
    float* crow = (float*)(asm_ + AT_CROW); // [64]

    const int q0 = blockIdx.x << 6;
    const int h = blockIdx.y, b = blockIdx.z;
    const int tid = threadIdx.x;
    const int tx = tid & 15, ty = tid >> 4;

    // stage Q (transposed: Qs[c][q])
#pragma unroll
    for (int i = 0; i < 4; i++) {
        int idx = tid + (i << 8);
        int r = idx >> 4, c4 = (idx & 15) << 2;
        float4 v = *(const float4*)&AQ[(size_t)(b * DT + q0 + r) * DD + h * DHD + c4];
        Qs[(c4 + 0) * 68 + r] = v.x; Qs[(c4 + 1) * 68 + r] = v.y;
        Qs[(c4 + 2) * 68 + r] = v.z; Qs[(c4 + 3) * 68 + r] = v.w;
    }
    if (tid < 64) { mrow[tid] = -1e30f; lrow[tid] = 0.0f; }
    __syncthreads();

    float acc[4][4] = {};                  // O accumulator: q = q0+tx*4+i, d = ty*4+j

    int kLo = q0 - (DWIN - 1);
    if (kLo < 0) kLo = 0;
    kLo &= ~63;
    for (int k0 = kLo; k0 <= q0; k0 += 64) {
        // stage K (transposed) and V (row-major)
#pragma unroll
        for (int i = 0; i < 4; i++) {
            int idx = tid + (i << 8);
            int r = idx >> 4, c4 = (idx & 15) << 2;
            float4 kv = *(const float4*)&AK[(size_t)(b * DT + k0 + r) * DD + h * DHD + c4];
            Ks[(c4 + 0) * 68 + r] = kv.x; Ks[(c4 + 1) * 68 + r] = kv.y;
            Ks[(c4 + 2) * 68 + r] = kv.z; Ks[(c4 + 3) * 68 + r] = kv.w;
            float4 vv = *(const float4*)&AV[(size_t)(b * DT + k0 + r) * DD + h * DHD + c4];
            *(float4*)&Vs[r * 68 + c4] = vv;
        }
        __syncthreads();

        // S tile: s[i][j] = q row (tx*4+i) . k row (ty*4+j)
        float s[4][4];
        {
            float (&acc)[4][4] = s;        // reuse FMA4x4 macro on s
#pragma unroll
            for (int i = 0; i < 4; i++)
#pragma unroll
                for (int j = 0; j < 4; j++) acc[i][j] = 0.0f;
#pragma unroll 16
            for (int cc = 0; cc < 64; cc++) {
                float4 a = *(const float4*)&Qs[cc * 68 + (tx << 2)];
                float4 bb = *(const float4*)&Ks[cc * 68 + (ty << 2)];
                FMA4x4(a, bb);
            }
        }
        // scale + mask + per-thread row max
#pragma unroll
        for (int i = 0; i < 4; i++) {
            const int q = q0 + (tx << 2) + i;
            float lm = -1e30f;
#pragma unroll
            for (int j = 0; j < 4; j++) {
                const int k = k0 + (ty << 2) + j;
                s[i][j] = (k <= q && q - k < DWIN) ? s[i][j] * 0.125f : -1e30f;
                lm = fmaxf(lm, s[i][j]);
            }
            red[ty * 64 + (tx << 2) + i] = lm;
        }
        __syncthreads();
        // reduce row max, update m / correction
        if (tid < 64) {
            float mc = red[tid];
#pragma unroll
            for (int t = 1; t < 16; t++) mc = fmaxf(mc, red[t * 64 + tid]);
            float mo = mrow[tid];
            float mn = fmaxf(mo, mc);
            crow[tid] = __expf(mo - mn);
            mrow[tid] = mn;
            lrow[tid] *= crow[tid];
        }
        __syncthreads();
        // P = exp(s - m), store transposed; partial row sums; rescale O
#pragma unroll
        for (int i = 0; i < 4; i++) {
            const int qi = (tx << 2) + i;
            const float mn = mrow[qi];
            float ls = 0.0f;
#pragma unroll
            for (int j = 0; j < 4; j++) {
                float p = __expf(s[i][j] - mn);
                Ps[((ty << 2) + j) * 68 + qi] = p;
                ls += p;
            }
            red[ty * 64 + qi] = ls;
            const float ci = crow[qi];
#pragma unroll
            for (int j = 0; j < 4; j++) acc[i][j] *= ci;
        }
        __syncthreads();
        if (tid < 64) {
            float ssum = 0.0f;
#pragma unroll
            for (int t = 0; t < 16; t++) ssum += red[t * 64 + tid];
            lrow[tid] += ssum;
        }
        // O += P @ V
#pragma unroll 16
        for (int kk = 0; kk < 64; kk++) {
            float4 a = *(const float4*)&Ps[kk * 68 + (tx << 2)];
            float4 bb = *(const float4*)&Vs[kk * 68 + (ty << 2)];
            FMA4x4(a, bb);
        }
        __syncthreads();
    }

    // finalize: O /= l
#pragma unroll
    for (int i = 0; i < 4; i++) {
        const float inv = 1.0f / lrow[(tx << 2) + i];
        const int q = q0 + (tx << 2) + i;
#pragma unroll
        for (int j = 0; j < 4; j++)
            AO[(size_t)(b * DT + q) * DD + h * DHD + (ty << 2) + j] = acc[i][j] * inv;
    }
}

// ---------------- host ----------------
extern "C" void kernel_launch(void* const* d_in, const int* in_sizes, int n_in,
                              void* d_out, int out_size) {
    const float* x      = (const float*)d_in[0];
    const float* meta   = (const float*)d_in[1];
    const float* lmm_w  = (const float*)d_in[2];
    const float* w_q    = (const float*)d_in[3];
    const float* w_k    = (const float*)d_in[4];
    const float* w_v    = (const float*)d_in[5];
    const float* w_lr   = (const float*)d_in[6];
    const float* swa_wq = (const float*)d_in[7];
    const float* swa_wk = (const float*)d_in[8];
    const float* swa_wv = (const float*)d_in[9];
    const float* swa_wo = (const float*)d_in[10];
    float* out = (float*)d_out;

    float *XM, *K, *V, *Q, *LR, *Z0, *X1, *Z1, *X2, *DY2, *DZ1, *DX1, *DZ0;
    float *Wn, *W1t, *Y1, *Y2, *AQ, *AK, *AV, *AO, *GP;
    cudaGetSymbolAddress((void**)&XM, g_XM);
    cudaGetSymbolAddress((void**)&K, g_K);
    cudaGetSymbolAddress((void**)&V, g_V);
    cudaGetSymbolAddress((void**)&Q, g_Q);
    cudaGetSymbolAddress((void**)&LR, g_LR);
    cudaGetSymbolAddress((void**)&Z0, g_Z0);
    cudaGetSymbolAddress((void**)&X1, g_X1);
    cudaGetSymbolAddress((void**)&Z1, g_Z1);
    cudaGetSymbolAddress((void**)&X2, g_X2);
    cudaGetSymbolAddress((void**)&DY2, g_DY2);
    cudaGetSymbolAddress((void**)&DZ1, g_DZ1);
    cudaGetSymbolAddress((void**)&DX1, g_DX1);
    cudaGetSymbolAddress((void**)&DZ0, g_DZ0);
    cudaGetSymbolAddress((void**)&Wn, g_Wn);
    cudaGetSymbolAddress((void**)&W1t, g_W1t);
    cudaGetSymbolAddress((void**)&Y1, g_Y1);
    cudaGetSymbolAddress((void**)&Y2, g_Y2);
    cudaGetSymbolAddress((void**)&AQ, g_AQ);
    cudaGetSymbolAddress((void**)&AK, g_AK);
    cudaGetSymbolAddress((void**)&AV, g_AV);
    cudaGetSymbolAddress((void**)&AO, g_AO);
    cudaGetSymbolAddress((void**)&GP, g_GP);

    cudaFuncSetAttribute(wm_nt3_k, cudaFuncAttributeMaxDynamicSharedMemorySize, WM_SMEM);
    cudaFuncSetAttribute(wm_gemm_k<0, 1>, cudaFuncAttributeMaxDynamicSharedMemorySize, WM_SMEM);
    cudaFuncSetAttribute(wm_gemm_k<0, 2>, cudaFuncAttributeMaxDynamicSharedMemorySize, WM_SMEM);
    cudaFuncSetAttribute(wm_gemm_k<0, 3>, cudaFuncAttributeMaxDynamicSharedMemorySize, WM_SMEM);
    cudaFuncSetAttribute(wm_gemm_k<1, 0>, cudaFuncAttributeMaxDynamicSharedMemorySize, WM_SMEM);
    cudaFuncSetAttribute(attn_fused_k, cudaFuncAttributeMaxDynamicSharedMemorySize, AT_SMEM);

    const dim3 gG(DN / 128, DD / 128);          // 33 x 4
    const dim3 gG3(DN / 128, DD / 128, 3);      // batched projections
    const dim3 gTN(DD / 128, DD / 128, NSPLIT); // 4 x 4 x 11
    const dim3 gAT(DT / 64, DH, DB);            // 33 x 8 x 2
    const int EW = (DN * DD + 255) / 256;

    // 1. concat meta + x ; transpose W1 for the NN gemm
    build_xm_k<<<(DN * DD / 4 + 255) / 256, 256>>>(x, meta, XM);
    transpose_k<<<dim3(16, 16), dim3(32, 8)>>>(lmm_w + DD * DD, W1t);
    // 2. projections (K, V, Q batched)
    wm_nt3_k<<<gG3, 256, WM_SMEM>>>(XM, w_k, w_v, w_q, K, V, Q);
    lr_proj_k<<<(DN * 32 + 255) / 256, 256>>>(XM, w_lr, LR);
    // 3. LMM forward on keys
    wm_gemm_k<0, 1><<<gG, 256, WM_SMEM>>>(K, lmm_w, nullptr, Z0, X1);
    wm_gemm_k<0, 1><<<gG, 256, WM_SMEM>>>(X1, lmm_w + DD * DD, nullptr, Z1, X2);
    // 4. backward
    grad_head_k<<<EW, 256>>>(X2, V, Z1, LR, DY2, DZ1);
    wm_gemm_k<1, 0><<<gTN, 256, WM_SMEM>>>(DZ1, X1, nullptr, GP + NSPLIT * DD * DD, nullptr); // dW1
    wm_gemm_k<0, 3><<<gG, 256, WM_SMEM>>>(DZ1, W1t, DY2, DX1, nullptr);                       // dx1
    bwd_act0_k<<<EW, 256>>>(DX1, Z0, DZ0);
    wm_gemm_k<1, 0><<<gTN, 256, WM_SMEM>>>(DZ0, K, nullptr, GP, nullptr);                     // dW0
    // 5. AdamW first step
    adamw_k<<<(NLAY * DD * DD + 255) / 256, 256>>>(lmm_w, Wn);
    // 6. retrieval with updated weights
    wm_gemm_k<0, 1><<<gG, 256, WM_SMEM>>>(Q, Wn, nullptr, Z0, Y1);
    wm_gemm_k<0, 1><<<gG, 256, WM_SMEM>>>(Y1, Wn + DD * DD, nullptr, Z1, Y2);
    // 7. sliding-window attention (fused flash-style: no score buffer)
    wm_nt3_k<<<gG3, 256, WM_SMEM>>>(Y2, swa_wq, swa_wk, swa_wv, AQ, AK, AV);
    attn_fused_k<<<gAT, 256, AT_SMEM>>>(AQ, AK, AV, AO);
    // 8. output projection, dropping meta rows
    wm_gemm_k<0, 2><<<gG, 256, WM_SMEM>>>(AO, swa_wo, nullptr, nullptr, out);
}

// round 16
// speedup vs baseline: 1.3816x; 1.0195x over previous
#include <cuda_runtime.h>
#include <cuda_bf16.h>
#include <cstdint>

// ---------------- problem constants ----------------
#define DB 2
#define DS 2048
#define DD 512
#define DM 64
#define DT 2112              // DM + DS
#define DN 4224              // DB * DT
#define DH 8
#define DHD 64
#define DWIN 512
#define NSPLIT 33
#define SPLITROWS 128        // DN / NSPLIT = 128 (2 chunks of 64)
#define NLAY 2
#define LRC 1e-3f
#define WDC 1e-2f
#define EPSC 1e-8f
#define MAXALR 0.01f

// warp-mma tile constants
#define ROWB 144             // bytes per smem tile row (64 bf16 = 128B + 16B pad)
#define TILEB (128 * ROWB)   // 18432 B per tile
#define BUFB (4 * TILEB)     // Ah, Al, Bh, Bl = 73728 B per buffer
#define WM_SMEM (2 * BUFB)   // double-buffered = 147456 B

// fused attention smem layout (bytes); tiles are [64][68] floats
#define AT_TILE (64 * 68 * 4)          // 17408
#define AT_QS 0
#define AT_KS (AT_TILE)
#define AT_PS (2 * AT_TILE)
#define AT_VS (3 * AT_TILE)
#define AT_RED (4 * AT_TILE)           // 16 x 64 floats = 4096
#define AT_MROW (AT_RED + 4096)        // 64 floats
#define AT_LROW (AT_MROW + 256)
#define AT_CROW (AT_LROW + 256)
#define AT_SMEM (AT_CROW + 256)        // 74496

// ---------------- scratch (device globals; no allocs allowed) ----------------
static __device__ float g_XM[DN * DD];
static __device__ float g_K[DN * DD];
static __device__ float g_V[DN * DD];
static __device__ float g_Q[DN * DD];
static __device__ float g_LR[DN];
static __device__ float g_Z0[DN * DD];
static __device__ float g_X1[DN * DD];
static __device__ float g_DY2[DN * DD];
static __device__ float g_DZ1[DN * DD];
static __device__ float g_DZ0[DN * DD];
static __device__ float g_Wn[NLAY * DD * DD];
static __device__ float g_W1t[DD * DD];
static __device__ float g_Y1[DN * DD];
static __device__ float g_Y2[DN * DD];
static __device__ float g_AQ[DN * DD];
static __device__ float g_AK[DN * DD];
static __device__ float g_AV[DN * DD];
static __device__ float g_AO[DN * DD];
static __device__ float g_GP[NLAY * NSPLIT * DD * DD];          // split-K grad partials

__device__ __forceinline__ float sigf(float z) { return 1.0f / (1.0f + __expf(-z)); }
__device__ __forceinline__ float silup(float z) {
    float s = sigf(z);
    return s * (1.0f + z * (1.0f - s));
}

// ================= warp-mma helpers (sm_80+ baseline PTX, no 'a' features) ======
__device__ __forceinline__ uint32_t smem_u32(const void* p) {
    uint32_t a;
    asm("{ .reg .u64 t; cvta.to.shared.u64 t, %1; cvt.u32.u64 %0, t; }" : "=r"(a) : "l"(p));
    return a;
}
__device__ __forceinline__ void mma16816(float* c, const uint32_t* a, const uint32_t* b) {
    asm volatile(
        "mma.sync.aligned.m16n8k16.row.col.f32.bf16.bf16.f32 "
        "{%0,%1,%2,%3}, {%4,%5,%6,%7}, {%8,%9}, {%0,%1,%2,%3};"
        : "+f"(c[0]), "+f"(c[1]), "+f"(c[2]), "+f"(c[3])
        : "r"(a[0]), "r"(a[1]), "r"(a[2]), "r"(a[3]), "r"(b[0]), "r"(b[1]));
}
__device__ __forceinline__ void ldsm4(uint32_t* r, uint32_t addr) {
    asm volatile("ldmatrix.sync.aligned.m8n8.x4.shared.b16 {%0,%1,%2,%3}, [%4];"
                 : "=r"(r[0]), "=r"(r[1]), "=r"(r[2]), "=r"(r[3]) : "r"(addr));
}
__device__ __forceinline__ void ldsm2(uint32_t* r, uint32_t addr) {
    asm volatile("ldmatrix.sync.aligned.m8n8.x2.shared.b16 {%0,%1}, [%2];"
                 : "=r"(r[0]), "=r"(r[1]) : "r"(addr));
}
// fp32 pair -> bf16x2 hi + bf16x2 lo (split-bf16)
__device__ __forceinline__ void cvt_hl(float a, float b, uint32_t& h, uint32_t& l) {
    __nv_bfloat162 th, tl;
    th.x = __float2bfloat16(a);
    th.y = __float2bfloat16(b);
    tl.x = __float2bfloat16(a - __bfloat162float(th.x));
    tl.y = __float2bfloat16(b - __bfloat162float(th.y));
    h = *reinterpret_cast<uint32_t*>(&th);
    l = *reinterpret_cast<uint32_t*>(&tl);
}

// ---- pipelined NT staging: load phase (gmem -> regs)
__device__ __forceinline__ void nt_ld(float4* r, const float* __restrict__ src,
                                      int row0, int k0, int tid) {
#pragma unroll
    for (int it = 0; it < 8; it++) {
        int idx = tid + (it << 8);            // 0..2047 float4s (128 rows x 16)
        int m = idx >> 4;
        int kq = (idx & 15) << 2;
        r[it] = *(const float4*)&src[(row0 + m) * DD + k0 + kq];
    }
}
// ---- pipelined NT staging: convert + store phase (regs -> bf16 hi/lo smem)
__device__ __forceinline__ void nt_st(char* th, char* tl, const float4* r, int tid) {
#pragma unroll
    for (int it = 0; it < 8; it++) {
        int idx = tid + (it << 8);
        int m = idx >> 4;
        int kq = (idx & 15) << 2;
        uint32_t h0, l0, h1, l1;
        cvt_hl(r[it].x, r[it].y, h0, l0);
        cvt_hl(r[it].z, r[it].w, h1, l1);
        uint32_t off = m * ROWB + (kq << 1);
        *(uint2*)(th + off) = make_uint2(h0, h1);
        *(uint2*)(tl + off) = make_uint2(l0, l1);
    }
}
// ---- staging transposed (TN mode): tile(row=i, k) = src[(kb+k)*DD + col0 + i]
__device__ __forceinline__ void stage_tn(const float* __restrict__ src, int col0, int kb,
                                         char* th, char* tl, int tid) {
    const int i = tid & 127;
    const int half = tid >> 7;                // 0,1
#pragma unroll
    for (int it = 0; it < 16; it++) {
        int k = (it << 2) + (half << 1);      // even 0..62
        float v0 = src[(kb + k) * DD + col0 + i];
        float v1 = src[(kb + k + 1) * DD + col0 + i];
        uint32_t h, l;
        cvt_hl(v0, v1, h, l);
        uint32_t off = i * ROWB + (k << 1);
        *(uint32_t*)(th + off) = h;
        *(uint32_t*)(tl + off) = l;
    }
}

// ---- mma over ks range [KS0, KS1) for the 2x4 warp grid
template <int KS0, int KS1>
__device__ __forceinline__ void mma_steps(float (&acc)[4][4][4],
                                          uint32_t aBase, uint32_t bBase) {
#pragma unroll
    for (int ks = KS0; ks < KS1; ks++) {
        const uint32_t kOff = (uint32_t)(ks << 5);   // 16 bf16 = 32B
        uint32_t ah[4][4], al[4][4], bh[4][2], bl[4][2];
#pragma unroll
        for (int mf = 0; mf < 4; mf++) {
            ldsm4(ah[mf], aBase + mf * (16 * ROWB) + kOff);
            ldsm4(al[mf], aBase + TILEB + mf * (16 * ROWB) + kOff);
        }
#pragma unroll
        for (int nf = 0; nf < 4; nf++) {
            ldsm2(bh[nf], bBase + nf * (8 * ROWB) + kOff);
            ldsm2(bl[nf], bBase + TILEB + nf * (8 * ROWB) + kOff);
        }
#pragma unroll
        for (int mf = 0; mf < 4; mf++)
#pragma unroll
            for (int nf = 0; nf < 4; nf++) {
                mma16816(acc[mf][nf], ah[mf], bh[nf]);
                mma16816(acc[mf][nf], ah[mf], bl[nf]);
                mma16816(acc[mf][nf], al[mf], bh[nf]);
            }
    }
}

// ================= 128x128 warp-mma GEMM body =================
// MODE 0 = NT (pipelined): C[M,N] = A[M,512] @ W[N,512]^T   (8 chunks of 64)
// MODE 1 = TN: C[i,j] = sum_n A[n,i] W[n,j] over split z (2 chunks of 64)
// EPI 0: Cz = z
// EPI 1: Cz = z ; Cx = A + silu(z)
// EPI 2: d_out drop-meta
// EPI 4: fused lmm-fwd2 + grad head: Cz=DY2, Cx=DZ1 (P1=V, P2=LR)
// EPI 5: fused dx1 + act0: Cz = (z + R) * silup(P1)       (P1=Z0, R=DY2)
// EPI 6: Cx = A + silu(z) only
template <int MODE, int EPI>
__device__ void wm_body(const float* __restrict__ A, const float* __restrict__ W,
                        const float* __restrict__ R, const float* __restrict__ P1,
                        const float* __restrict__ P2,
                        float* __restrict__ Cz, float* __restrict__ Cx) {
    extern __shared__ char sm[];
    const uint32_t sb = smem_u32(sm);

    const int tid = threadIdx.x;
    const int warp = tid >> 5, lane = tid & 31;
    const int wm = warp >> 2, wn = warp & 3;       // 2 x 4 warp grid
    const int m0 = blockIdx.x << 7;
    const int n0 = blockIdx.y << 7;
    const int kb0 = (MODE == 1) ? blockIdx.z * SPLITROWS : 0;
    const int NCH = (MODE == 1) ? (SPLITROWS / 64) : (DD / 64);
    float* Czp = (MODE == 1) ? (Cz + blockIdx.z * DD * DD) : Cz;

    float acc[4][4][4];
#pragma unroll
    for (int mf = 0; mf < 4; mf++)
#pragma unroll
        for (int nf = 0; nf < 4; nf++)
#pragma unroll
            for (int e = 0; e < 4; e++) acc[mf][nf][e] = 0.0f;

    const int ar = (lane & 7) + ((lane >> 3) & 1) * 8;
    const int acol = (lane >> 4) << 3;
    const int br = lane & 7;
    const int bcol = ((lane >> 3) & 1) << 3;
    const uint32_t aBase0 = sb + (wm * 64 + ar) * ROWB + acol * 2;
    const uint32_t bBase0 = sb + 2 * TILEB + (wn * 32 + br) * ROWB + bcol * 2;

    if (MODE == 0) {
        float4 pa[8], pb[8];
        nt_ld(pa, A, m0, 0, tid);
        nt_ld(pb, W, n0, 0, tid);
        nt_st(sm, sm + TILEB, pa, tid);
        nt_st(sm + 2 * TILEB, sm + 3 * TILEB, pb, tid);
        __syncthreads();
        for (int c = 0; c < NCH; c++) {
            const uint32_t bo = (uint32_t)(c & 1) * BUFB;
            char* nb = sm + ((c & 1) ^ 1) * BUFB;
            const int k1 = (c + 1) << 6;
            if (c + 1 < NCH) nt_ld(pa, A, m0, k1, tid);
            mma_steps<0, 2>(acc, aBase0 + bo, bBase0 + bo);
            if (c + 1 < NCH) {
                nt_st(nb, nb + TILEB, pa, tid);
                nt_ld(pb, W, n0, k1, tid);
            }
            mma_steps<2, 4>(acc, aBase0 + bo, bBase0 + bo);
            if (c + 1 < NCH) nt_st(nb + 2 * TILEB, nb + 3 * TILEB, pb, tid);
            __syncthreads();
        }
    } else {
        for (int c = 0; c < NCH; c++) {
            const int k0 = kb0 + (c << 6);
            char* cb = sm + (c & 1) * BUFB;
            stage_tn(A, m0, k0, cb, cb + TILEB, tid);
            stage_tn(W, n0, k0, cb + 2 * TILEB, cb + 3 * TILEB, tid);
            __syncthreads();
            const uint32_t bo = (uint32_t)(c & 1) * BUFB;
            mma_steps<0, 4>(acc, aBase0 + bo, bBase0 + bo);
            __syncthreads();
        }
    }

    const int erow = (lane >> 2);
    const int ecol = (lane & 3) << 1;
#pragma unroll
    for (int mf = 0; mf < 4; mf++)
#pragma unroll
        for (int nf = 0; nf < 4; nf++) {
            const int colg = n0 + wn * 32 + nf * 8 + ecol;
#pragma unroll
            for (int h = 0; h < 2; h++) {
                const int rowg = m0 + wm * 64 + mf * 16 + erow + h * 8;
                float zx = acc[mf][nf][2 * h];
                float zy = acc[mf][nf][2 * h + 1];
                if (EPI == 0) {
                    *(float2*)&Czp[rowg * DD + colg] = make_float2(zx, zy);
                } else if (EPI == 1) {
                    *(float2*)&Czp[rowg * DD + colg] = make_float2(zx, zy);
                    float2 a = *(const float2*)&A[rowg * DD + colg];
                    *(float2*)&Cx[rowg * DD + colg] =
                        make_float2(a.x + zx * sigf(zx), a.y + zy * sigf(zy));
                } else if (EPI == 4) {
                    float2 a = *(const float2*)&A[rowg * DD + colg];
                    float2 vv = *(const float2*)&P1[rowg * DD + colg];
                    float cc = (2.0f / (float)DD) * P2[rowg];
                    float x2x = a.x + zx * sigf(zx);
                    float x2y = a.y + zy * sigf(zy);
                    float dyx = cc * (x2x - vv.x);
                    float dyy = cc * (x2y - vv.y);
                    *(float2*)&Czp[rowg * DD + colg] = make_float2(dyx, dyy);
                    *(float2*)&Cx[rowg * DD + colg] =
                        make_float2(dyx * silup(zx), dyy * silup(zy));
                } else if (EPI == 5) {
                    float2 r = *(const float2*)&R[rowg * DD + colg];
                    float2 z0 = *(const float2*)&P1[rowg * DD + colg];
                    *(float2*)&Czp[rowg * DD + colg] =
                        make_float2((zx + r.x) * silup(z0.x), (zy + r.y) * silup(z0.y));
                } else if (EPI == 6) {
                    float2 a = *(const float2*)&A[rowg * DD + colg];
                    *(float2*)&Cx[rowg * DD + colg] =
                        make_float2(a.x + zx * sigf(zx), a.y + zy * sigf(zy));
                } else {   // EPI 2: drop meta rows -> d_out
                    const int bb = rowg / DT, t = rowg - bb * DT;
                    if (t >= DM)
                        *(float2*)&Cx[(bb * DS + (t - DM)) * DD + colg] = make_float2(zx, zy);
                }
            }
        }
}

template <int MODE, int EPI>
__global__ void __launch_bounds__(256, 1) wm_gemm_k(
    const float* __restrict__ A, const float* __restrict__ W,
    const float* __restrict__ R, const float* __restrict__ P1,
    const float* __restrict__ P2,
    float* __restrict__ Cz, float* __restrict__ Cx) {
    wm_body<MODE, EPI>(A, W, R, P1, P2, Cz, Cx);
}

__global__ void __launch_bounds__(256, 1) wm_nt3_k(
    const float* __restrict__ A,
    const float* __restrict__ W0, const float* __restrict__ W1, const float* __restrict__ W2,
    float* __restrict__ C0, float* __restrict__ C1, float* __restrict__ C2) {
    const float* W = (blockIdx.z == 0) ? W0 : (blockIdx.z == 1 ? W1 : W2);
    float* C = (blockIdx.z == 0) ? C0 : (blockIdx.z == 1 ? C1 : C2);
    wm_body<0, 0>(A, W, nullptr, nullptr, nullptr, C, nullptr);
}

// ---------------- 512x512 transpose (for NN -> NT) ----------------
__global__ void transpose_k(const float* __restrict__ in, float* __restrict__ outp) {
    __shared__ float t[32][33];
    int x = blockIdx.x * 32 + threadIdx.x;
    int y = blockIdx.y * 32 + threadIdx.y;
#pragma unroll
    for (int j = 0; j < 32; j += 8) t[threadIdx.y + j][threadIdx.x] = in[(y + j) * DD + x];
    __syncthreads();
    x = blockIdx.y * 32 + threadIdx.x;
    y = blockIdx.x * 32 + threadIdx.y;
#pragma unroll
    for (int j = 0; j < 32; j += 8) outp[(y + j) * DD + x] = t[threadIdx.x][threadIdx.y + j];
}

// ---------------- build xm = concat(meta, x) ----------------
__global__ void build_xm_k(const float* __restrict__ x, const float* __restrict__ meta,
                           float* __restrict__ XM) {
    int idx = blockIdx.x * blockDim.x + threadIdx.x;
    if (idx >= DN * DD / 4) return;
    int e = idx << 2;
    int n = e / DD, d = e - n * DD;
    int b = n / DT, t = n - b * DT;
    float4 v;
    if (t < DM) v = *(const float4*)&meta[t * DD + d];
    else        v = *(const float4*)&x[(b * DS + (t - DM)) * DD + d];
    *(float4*)&XM[e] = v;
}

// ---------------- adaptive lr ----------------
__global__ void lr_proj_k(const float* __restrict__ XM, const float* __restrict__ wlr,
                          float* __restrict__ out) {
    int warp = (blockIdx.x * blockDim.x + threadIdx.x) >> 5;
    int lane = threadIdx.x & 31;
    if (warp >= DN) return;
    const float* xr = XM + warp * DD;
    float s = 0.0f;
#pragma unroll
    for (int i = 0; i < DD / 32; i++) s = fmaf(xr[lane + i * 32], wlr[lane + i * 32], s);
#pragma unroll
    for (int o = 16; o > 0; o >>= 1) s += __shfl_xor_sync(0xffffffffu, s, o);
    if (lane == 0) out[warp] = MAXALR * sigf(s);
}

// ---------------- reduce split-K partials + AdamW ----------------
__global__ void adamw_k(const float* __restrict__ W, float* __restrict__ Wn) {
    int idx = blockIdx.x * blockDim.x + threadIdx.x;
    if (idx >= NLAY * DD * DD) return;
    int l = idx / (DD * DD);
    int e = idx - l * (DD * DD);
    const float* gp = g_GP + l * NSPLIT * DD * DD;
    float g = 0.0f;
#pragma unroll 4
    for (int s = 0; s < NSPLIT; s++) g += gp[s * DD * DD + e];
    g *= (1.0f / 16.0f);
    float w = W[idx];
    Wn[idx] = w * (1.0f - LRC * WDC) - LRC * g / (fabsf(g) + EPSC);
}

#define FMA4x4(a, bb) do { \
    acc[0][0] = fmaf(a.x, bb.x, acc[0][0]); acc[0][1] = fmaf(a.x, bb.y, acc[0][1]); \
    acc[0][2] = fmaf(a.x, bb.z, acc[0][2]); acc[0][3] = fmaf(a.x, bb.w, acc[0][3]); \
    acc[1][0] = fmaf(a.y, bb.x, acc[1][0]); acc[1][1] = fmaf(a.y, bb.y, acc[1][1]); \
    acc[1][2] = fmaf(a.y, bb.z, acc[1][2]); acc[1][3] = fmaf(a.y, bb.w, acc[1][3]); \
    acc[2][0] = fmaf(a.z, bb.x, acc[2][0]); acc[2][1] = fmaf(a.z, bb.y, acc[2][1]); \
    acc[2][2] = fmaf(a.z, bb.z, acc[2][2]); acc[2][3] = fmaf(a.z, bb.w, acc[2][3]); \
    acc[3][0] = fmaf(a.w, bb.x, acc[3][0]); acc[3][1] = fmaf(a.w, bb.y, acc[3][1]); \
    acc[3][2] = fmaf(a.w, bb.z, acc[3][2]); acc[3][3] = fmaf(a.w, bb.w, acc[3][3]); \
} while (0)

// ================ fused flash-style sliding-window attention ================
// One CTA = 64 q rows of one (b, h). Online softmax; no score buffer.
__global__ void __launch_bounds__(256, 2) attn_fused_k(
    const float* __restrict__ AQ, const float* __restrict__ AK,
    const float* __restrict__ AV, float* __restrict__ AO) {
    extern __shared__ char asm_[];
    float* Qs = (float*)(asm_ + AT_QS);     // [64][68]  (c-major: Qs[c][q])
    float* Ks = (float*)(asm_ + AT_KS);     // [64][68]  (Ks[c][k])
    float* Ps = (float*)(asm_ + AT_PS);     // [64][68]  (Ps[k][q])
    float* Vs = (float*)(asm_ + AT_VS);     // [64][68]  (Vs[k][d])
    float* red = (float*)(asm_ + AT_RED);   // [16][64]
    float* mrow = (float*)(asm_ + AT_MROW); // [64]
    float* lrow = (float*)(asm_ + AT_LROW); // [64]
    float* crow = (float*)(asm_ + AT_CROW); // [64]

    const int q0 = blockIdx.x << 6;
    const int h = blockIdx.y, b = blockIdx.z;
    const int tid = threadIdx.x;
    const int tx = tid & 15, ty = tid >> 4;

#pragma unroll
    for (int i = 0; i < 4; i++) {
        int idx = tid + (i << 8);
        int r = idx >> 4, c4 = (idx & 15) << 2;
        float4 v = *(const float4*)&AQ[(size_t)(b * DT + q0 + r) * DD + h * DHD + c4];
        Qs[(c4 + 0) * 68 + r] = v.x; Qs[(c4 + 1) * 68 + r] = v.y;
        Qs[(c4 + 2) * 68 + r] = v.z; Qs[(c4 + 3) * 68 + r] = v.w;
    }
    if (tid < 64) { mrow[tid] = -1e30f; lrow[tid] = 0.0f; }
    __syncthreads();

    float acc[4][4] = {};

    int kLo = q0 - (DWIN - 1);
    if (kLo < 0) kLo = 0;
    kLo &= ~63;
    for (int k0 = kLo; k0 <= q0; k0 += 64) {
#pragma unroll
        for (int i = 0; i < 4; i++) {
            int idx = tid + (i << 8);
            int r = idx >> 4, c4 = (idx & 15) << 2;
            float4 kv = *(const float4*)&AK[(size_t)(b * DT + k0 + r) * DD + h * DHD + c4];
            Ks[(c4 + 0) * 68 + r] = kv.x; Ks[(c4 + 1) * 68 + r] = kv.y;
            Ks[(c4 + 2) * 68 + r] = kv.z; Ks[(c4 + 3) * 68 + r] = kv.w;
            float4 vv = *(const float4*)&AV[(size_t)(b * DT + k0 + r) * DD + h * DHD + c4];
            *(float4*)&Vs[r * 68 + c4] = vv;
        }
        __syncthreads();

        float s[4][4];
        {
            float (&acc)[4][4] = s;
#pragma unroll
            for (int i = 0; i < 4; i++)
#pragma unroll
                for (int j = 0; j < 4; j++) acc[i][j] = 0.0f;
#pragma unroll 16
            for (int cc = 0; cc < 64; cc++) {
                float4 a = *(const float4*)&Qs[cc * 68 + (tx << 2)];
                float4 bb = *(const float4*)&Ks[cc * 68 + (ty << 2)];
                FMA4x4(a, bb);
            }
        }
#pragma unroll
        for (int i = 0; i < 4; i++) {
            const int q = q0 + (tx << 2) + i;
            float lm = -1e30f;
#pragma unroll
            for (int j = 0; j < 4; j++) {
                const int k = k0 + (ty << 2) + j;
                s[i][j] = (k <= q && q - k < DWIN) ? s[i][j] * 0.125f : -1e30f;
                lm = fmaxf(lm, s[i][j]);
            }
            red[ty * 64 + (tx << 2) + i] = lm;
        }
        __syncthreads();
        if (tid < 64) {
            float mc = red[tid];
#pragma unroll
            for (int t = 1; t < 16; t++) mc = fmaxf(mc, red[t * 64 + tid]);
            float mo = mrow[tid];
            float mn = fmaxf(mo, mc);
            crow[tid] = __expf(mo - mn);
            mrow[tid] = mn;
            lrow[tid] *= crow[tid];
        }
        __syncthreads();
#pragma unroll
        for (int i = 0; i < 4; i++) {
            const int qi = (tx << 2) + i;
            const float mn = mrow[qi];
            float ls = 0.0f;
#pragma unroll
            for (int j = 0; j < 4; j++) {
                float p = __expf(s[i][j] - mn);
                Ps[((ty << 2) + j) * 68 + qi] = p;
                ls += p;
            }
            red[ty * 64 + qi] = ls;
            const float ci = crow[qi];
#pragma unroll
            for (int j = 0; j < 4; j++) acc[i][j] *= ci;
        }
        __syncthreads();
        if (tid < 64) {
            float ssum = 0.0f;
#pragma unroll
            for (int t = 0; t < 16; t++) ssum += red[t * 64 + tid];
            lrow[tid] += ssum;
        }
#pragma unroll 16
        for (int kk = 0; kk < 64; kk++) {
            float4 a = *(const float4*)&Ps[kk * 68 + (tx << 2)];
            float4 bb = *(const float4*)&Vs[kk * 68 + (ty << 2)];
            FMA4x4(a, bb);
        }
        __syncthreads();
    }

#pragma unroll
    for (int i = 0; i < 4; i++) {
        const float inv = 1.0f / lrow[(tx << 2) + i];
        const int q = q0 + (tx << 2) + i;
#pragma unroll
        for (int j = 0; j < 4; j++)
            AO[(size_t)(b * DT + q) * DD + h * DHD + (ty << 2) + j] = acc[i][j] * inv;
    }
}

// ---------------- host ----------------
extern "C" void kernel_launch(void* const* d_in, const int* in_sizes, int n_in,
                              void* d_out, int out_size) {
    const float* x      = (const float*)d_in[0];
    const float* meta   = (const float*)d_in[1];
    const float* lmm_w  = (const float*)d_in[2];
    const float* w_q    = (const float*)d_in[3];
    const float* w_k    = (const float*)d_in[4];
    const float* w_v    = (const float*)d_in[5];
    const float* w_lr   = (const float*)d_in[6];
    const float* swa_wq = (const float*)d_in[7];
    const float* swa_wk = (const float*)d_in[8];
    const float* swa_wv = (const float*)d_in[9];
    const float* swa_wo = (const float*)d_in[10];
    float* out = (float*)d_out;

    float *XM, *K, *V, *Q, *LR, *Z0, *X1, *DY2, *DZ1, *DZ0;
    float *Wn, *W1t, *Y1, *Y2, *AQ, *AK, *AV, *AO, *GP;
    cudaGetSymbolAddress((void**)&XM, g_XM);
    cudaGetSymbolAddress((void**)&K, g_K);
    cudaGetSymbolAddress((void**)&V, g_V);
    cudaGetSymbolAddress((void**)&Q, g_Q);
    cudaGetSymbolAddress((void**)&LR, g_LR);
    cudaGetSymbolAddress((void**)&Z0, g_Z0);
    cudaGetSymbolAddress((void**)&X1, g_X1);
    cudaGetSymbolAddress((void**)&DY2, g_DY2);
    cudaGetSymbolAddress((void**)&DZ1, g_DZ1);
    cudaGetSymbolAddress((void**)&DZ0, g_DZ0);
    cudaGetSymbolAddress((void**)&Wn, g_Wn);
    cudaGetSymbolAddress((void**)&W1t, g_W1t);
    cudaGetSymbolAddress((void**)&Y1, g_Y1);
    cudaGetSymbolAddress((void**)&Y2, g_Y2);
    cudaGetSymbolAddress((void**)&AQ, g_AQ);
    cudaGetSymbolAddress((void**)&AK, g_AK);
    cudaGetSymbolAddress((void**)&AV, g_AV);
    cudaGetSymbolAddress((void**)&AO, g_AO);
    cudaGetSymbolAddress((void**)&GP, g_GP);

    cudaFuncSetAttribute(wm_nt3_k, cudaFuncAttributeMaxDynamicSharedMemorySize, WM_SMEM);
    cudaFuncSetAttribute(wm_gemm_k<0, 1>, cudaFuncAttributeMaxDynamicSharedMemorySize, WM_SMEM);
    cudaFuncSetAttribute(wm_gemm_k<0, 2>, cudaFuncAttributeMaxDynamicSharedMemorySize, WM_SMEM);
    cudaFuncSetAttribute(wm_gemm_k<0, 4>, cudaFuncAttributeMaxDynamicSharedMemorySize, WM_SMEM);
    cudaFuncSetAttribute(wm_gemm_k<0, 5>, cudaFuncAttributeMaxDynamicSharedMemorySize, WM_SMEM);
    cudaFuncSetAttribute(wm_gemm_k<0, 6>, cudaFuncAttributeMaxDynamicSharedMemorySize, WM_SMEM);
    cudaFuncSetAttribute(wm_gemm_k<1, 0>, cudaFuncAttributeMaxDynamicSharedMemorySize, WM_SMEM);
    cudaFuncSetAttribute(attn_fused_k, cudaFuncAttributeMaxDynamicSharedMemorySize, AT_SMEM);

    const dim3 gG(DN / 128, DD / 128);          // 33 x 4
    const dim3 gG3(DN / 128, DD / 128, 3);      // batched projections
    const dim3 gTN(DD / 128, DD / 128, NSPLIT); // 4 x 4 x 33 = 528 CTAs
    const dim3 gAT(DT / 64, DH, DB);            // 33 x 8 x 2

    // 1. concat meta + x ; transpose W1 for the NN gemm
    build_xm_k<<<(DN * DD / 4 + 255) / 256, 256>>>(x, meta, XM);
    transpose_k<<<dim3(16, 16), dim3(32, 8)>>>(lmm_w + DD * DD, W1t);
    // 2. projections (K, V, Q batched)
    wm_nt3_k<<<gG3, 256, WM_SMEM>>>(XM, w_k, w_v, w_q, K, V, Q);
    lr_proj_k<<<(DN * 32 + 255) / 256, 256>>>(XM, w_lr, LR);
    // 3. LMM forward layer 0 (save Z0, X1)
    wm_gemm_k<0, 1><<<gG, 256, WM_SMEM>>>(K, lmm_w, nullptr, nullptr, nullptr, Z0, X1);
    // 3b+4a fused: LMM layer 1 fwd + head grad + act1 bwd -> DY2, DZ1
    wm_gemm_k<0, 4><<<gG, 256, WM_SMEM>>>(X1, lmm_w + DD * DD, nullptr, V, LR, DY2, DZ1);
    // 4. backward GEMMs
    wm_gemm_k<1, 0><<<gTN, 256, WM_SMEM>>>(DZ1, X1, nullptr, nullptr, nullptr,
                                           GP + NSPLIT * DD * DD, nullptr);        // dW1
    wm_gemm_k<0, 5><<<gG, 256, WM_SMEM>>>(DZ1, W1t, DY2, Z0, nullptr, DZ0, nullptr); // dx1+act0
    wm_gemm_k<1, 0><<<gTN, 256, WM_SMEM>>>(DZ0, K, nullptr, nullptr, nullptr, GP, nullptr); // dW0
    // 5. AdamW first step
    adamw_k<<<(NLAY * DD * DD + 255) / 256, 256>>>(lmm_w, Wn);
    // 6. retrieval with updated weights (silu-only epilogues)
    wm_gemm_k<0, 6><<<gG, 256, WM_SMEM>>>(Q, Wn, nullptr, nullptr, nullptr, nullptr, Y1);
    wm_gemm_k<0, 6><<<gG, 256, WM_SMEM>>>(Y1, Wn + DD * DD, nullptr, nullptr, nullptr, nullptr, Y2);
    // 7. sliding-window attention (fused flash-style)
    wm_nt3_k<<<gG3, 256, WM_SMEM>>>(Y2, swa_wq, swa_wk, swa_wv, AQ, AK, AV);
    attn_fused_k<<<gAT, 256, AT_SMEM>>>(AQ, AK, AV, AO);
    // 8. output projection, dropping meta rows
    wm_gemm_k<0, 2><<<gG, 256, WM_SMEM>>>(AO, swa_wo, nullptr, nullptr, nullptr, nullptr, out);
}